// round 12
// baseline (speedup 1.0000x reference)
#include <cuda_runtime.h>
#include <cuda_bf16.h>
#include <stdint.h>

// ReBasedLinearAttention: B=2, L=2048, D=1024, H=16, FD=16, HD=64
// mma.sync bf16 hi/lo (3-MMA fp32 emulation).
// Round 12: GEMMs at 512 threads (4m x 4n warps, 32x32 warp tile, occ 2
// -> 8 warps/SMSP) to attack latency-bound profile. Attention = round-11.

#define Bb 2
#define Ll 2048
#define Dd 1024
#define Hh 16
#define BL (Bb * Ll)

typedef unsigned long long ull;
typedef __nv_bfloat16 bf16;

// ---------------- scratch ----------------
__device__ bf16 g_hhi[BL * 1024];
__device__ bf16 g_hlo[BL * 1024];
__device__ bf16 g_qhi[BL * 256];
__device__ bf16 g_qlo[BL * 256];
__device__ bf16 g_khi[BL * 256];
__device__ bf16 g_klo[BL * 256];
__device__ bf16 g_vhi[BL * 1024];
__device__ bf16 g_vlo[BL * 1024];
__device__ bf16 g_ohi[BL * 1024];
__device__ bf16 g_olo[BL * 1024];

__device__ bf16 g_wqt_hi[256 * 1024];
__device__ bf16 g_wqt_lo[256 * 1024];
__device__ bf16 g_wkt_hi[256 * 1024];
__device__ bf16 g_wkt_lo[256 * 1024];
__device__ bf16 g_wvt_hi[1024 * 1024];
__device__ bf16 g_wvt_lo[1024 * 1024];
__device__ bf16 g_wot_hi[1024 * 1024];
__device__ bf16 g_wot_lo[1024 * 1024];

// ---------------- PTX helpers ----------------
__device__ __forceinline__ uint32_t smem_u32(const void* p) {
    uint32_t a;
    asm("{ .reg .u64 t; cvta.to.shared.u64 t, %1; cvt.u32.u64 %0, t; }" : "=r"(a) : "l"(p));
    return a;
}
__device__ __forceinline__ void cp_async16(uint32_t saddr, const void* gaddr) {
    asm volatile("cp.async.cg.shared.global [%0], [%1], 16;" :: "r"(saddr), "l"(gaddr) : "memory");
}
__device__ __forceinline__ void cp_commit() {
    asm volatile("cp.async.commit_group;" ::: "memory");
}
__device__ __forceinline__ void cp_wait0() {
    asm volatile("cp.async.wait_group 0;" ::: "memory");
}
__device__ __forceinline__ void ldsm_x4(uint32_t& r0, uint32_t& r1, uint32_t& r2, uint32_t& r3,
                                        uint32_t addr) {
    asm volatile("ldmatrix.sync.aligned.m8n8.x4.shared.b16 {%0,%1,%2,%3}, [%4];"
                 : "=r"(r0), "=r"(r1), "=r"(r2), "=r"(r3) : "r"(addr));
}
__device__ __forceinline__ void ldsm_x4_t(uint32_t& r0, uint32_t& r1, uint32_t& r2, uint32_t& r3,
                                          uint32_t addr) {
    asm volatile("ldmatrix.sync.aligned.m8n8.x4.trans.shared.b16 {%0,%1,%2,%3}, [%4];"
                 : "=r"(r0), "=r"(r1), "=r"(r2), "=r"(r3) : "r"(addr));
}
__device__ __forceinline__ void mma16816(float c[4], uint32_t a0, uint32_t a1, uint32_t a2,
                                         uint32_t a3, uint32_t b0, uint32_t b1) {
    asm volatile(
        "mma.sync.aligned.m16n8k16.row.col.f32.bf16.bf16.f32 "
        "{%0,%1,%2,%3}, {%4,%5,%6,%7}, {%8,%9}, {%0,%1,%2,%3};"
        : "+f"(c[0]), "+f"(c[1]), "+f"(c[2]), "+f"(c[3])
        : "r"(a0), "r"(a1), "r"(a2), "r"(a3), "r"(b0), "r"(b1));
}
__device__ __forceinline__ uint32_t packbf(float flo, float fhi) {
    uint32_t r;
    asm("cvt.rn.bf16x2.f32 %0, %1, %2;" : "=r"(r) : "f"(fhi), "f"(flo));
    return r;
}
__device__ __forceinline__ float bflo(uint32_t p) { return __uint_as_float(p << 16); }
__device__ __forceinline__ float bfhi(uint32_t p) { return __uint_as_float(p & 0xffff0000u); }

// ---------------------------------------------------------------------------
// Conversions: z in [0,3] -> weight transpose+split; z == 4 -> hidden row split.
// ---------------------------------------------------------------------------
__global__ void convert_all(const float* __restrict__ hidden,
                            const float* __restrict__ Wq, const float* __restrict__ Wk,
                            const float* __restrict__ Wv, const float* __restrict__ Wo,
                            bf16* __restrict__ hh, bf16* __restrict__ hl,
                            bf16* __restrict__ qh, bf16* __restrict__ ql,
                            bf16* __restrict__ kh, bf16* __restrict__ kl,
                            bf16* __restrict__ vh, bf16* __restrict__ vl,
                            bf16* __restrict__ oh, bf16* __restrict__ ol)
{
    const int z = blockIdx.z;
    const int tid = threadIdx.y * 32 + threadIdx.x;
    if (z == 4) {
        int base = (blockIdx.y * (int)gridDim.x + blockIdx.x) * 1024 + tid * 4;
#pragma unroll
        for (int u = 0; u < 4; u++) {
            int i = base + u;
            float4 v = ((const float4*)hidden)[i];
            float vv[4] = {v.x, v.y, v.z, v.w};
            bf16 hhv[4], llv[4];
#pragma unroll
            for (int j = 0; j < 4; j++) {
                bf16 hb = __float2bfloat16(vv[j]);
                hhv[j] = hb;
                llv[j] = __float2bfloat16(vv[j] - __bfloat162float(hb));
            }
            *(ull*)&hh[(size_t)i * 4] = *(ull*)hhv;
            *(ull*)&hl[(size_t)i * 4] = *(ull*)llv;
        }
        return;
    }
    const int N = (z < 2) ? 256 : 1024;
    if (blockIdx.x * 32 >= N) return;
    const float* W = (z == 0) ? Wq : (z == 1) ? Wk : (z == 2) ? Wv : Wo;
    bf16* thi = (z == 0) ? qh : (z == 1) ? kh : (z == 2) ? vh : oh;
    bf16* tlo = (z == 0) ? ql : (z == 1) ? kl : (z == 2) ? vl : ol;

    __shared__ float t[32][33];
    int n0 = blockIdx.x * 32, k0 = blockIdx.y * 32;
    int tx = threadIdx.x, ty = threadIdx.y;
#pragma unroll
    for (int i = 0; i < 4; i++)
        t[ty + i * 8][tx] = W[(size_t)(k0 + ty + i * 8) * N + n0 + tx];
    __syncthreads();
#pragma unroll
    for (int i = 0; i < 4; i++) {
        int r = ty + i * 8;
        float v = t[tx][r];
        bf16 h = __float2bfloat16(v);
        bf16 l = __float2bfloat16(v - __bfloat162float(h));
        thi[(size_t)(n0 + r) * 1024 + k0 + tx] = h;
        tlo[(size_t)(n0 + r) * 1024 + k0 + tx] = l;
    }
}

// ---------------------------------------------------------------------------
// GEMM core (128x128 tile, 512 threads = 4m x 4n warps, 32x32 warp tile,
// BK=32, double buffer, 1 sync/stage, occ 2 -> 8 warps/SMSP).
// ---------------------------------------------------------------------------
#define ROWB 80
#define MATB (128 * ROWB)
#define STAGEB (4 * MATB)
#define GEMM_SMEM (2 * STAGEB)

#define LOAD_STAGE(s, buf)                                                              \
    do {                                                                                \
        const int k0 = (s) * 32;                                                        \
        const uint32_t sb_ = sbase + (buf) * STAGEB;                                    \
        _Pragma("unroll")                                                               \
        for (int t = 0; t < 4; t++) {                                                   \
            int idx = t * 512 + tid;                                                    \
            int mat = idx >> 9;                                                         \
            int rem = idx & 511;                                                        \
            int row = rem >> 2;                                                         \
            int kc = rem & 3;                                                           \
            const bf16* src = (mat == 0) ? Ahi : (mat == 1) ? Alo                       \
                             : (mat == 2) ? Bhi : Blo;                                  \
            int grow = ((mat < 2) ? rowBase : colBase) + row;                           \
            const bf16* g = src + (size_t)grow * 1024 + k0 + kc * 8;                    \
            uint32_t sa = sb_ + mat * MATB + row * ROWB + kc * 16;                      \
            cp_async16(sa, g);                                                          \
        }                                                                               \
        cp_commit();                                                                    \
    } while (0)

#define GEMM_MAINLOOP()                                                                 \
    LOAD_STAGE(0, 0);                                                                   \
    for (int s = 0; s < 32; s++) {                                                      \
        cp_wait0();                                                                     \
        __syncthreads();                                                                \
        if (s + 1 < 32) LOAD_STAGE(s + 1, (s + 1) & 1);                                 \
        const uint32_t sb = sbase + (s & 1) * STAGEB;                                   \
        _Pragma("unroll")                                                               \
        for (int s2 = 0; s2 < 2; s2++) {                                                \
            const uint32_t kbyte = s2 * 32 + lkb;                                       \
            uint32_t Ah[2][4], Al[2][4];                                                \
            _Pragma("unroll")                                                           \
            for (int mf = 0; mf < 2; mf++) {                                            \
                uint32_t ra = sb + (uint32_t)((wm * 32 + mf * 16 + lrow) * ROWB) + kbyte; \
                ldsm_x4(Ah[mf][0], Ah[mf][1], Ah[mf][2], Ah[mf][3], ra);                \
                ldsm_x4(Al[mf][0], Al[mf][1], Al[mf][2], Al[mf][3], ra + MATB);         \
            }                                                                           \
            _Pragma("unroll")                                                           \
            for (int nf2 = 0; nf2 < 2; nf2++) {                                         \
                uint32_t rb = sb + 2 * MATB +                                           \
                              (uint32_t)((wn * 32 + nf2 * 16 + lrow) * ROWB) + kbyte;   \
                uint32_t p0, p1, p2, p3, q0, q1, q2, q3;                                \
                ldsm_x4(p0, p1, p2, p3, rb);            /* Bh: frags (p0,p2),(p1,p3) */ \
                ldsm_x4(q0, q1, q2, q3, rb + MATB);     /* Bl */                        \
                _Pragma("unroll")                                                       \
                for (int mf = 0; mf < 2; mf++) {                                        \
                    mma16816(acc[mf][nf2 * 2 + 0], Ah[mf][0], Ah[mf][1], Ah[mf][2], Ah[mf][3], p0, p2); \
                    mma16816(acc[mf][nf2 * 2 + 1], Ah[mf][0], Ah[mf][1], Ah[mf][2], Ah[mf][3], p1, p3); \
                }                                                                       \
                _Pragma("unroll")                                                       \
                for (int mf = 0; mf < 2; mf++) {                                        \
                    mma16816(acc[mf][nf2 * 2 + 0], Ah[mf][0], Ah[mf][1], Ah[mf][2], Ah[mf][3], q0, q2); \
                    mma16816(acc[mf][nf2 * 2 + 1], Ah[mf][0], Ah[mf][1], Ah[mf][2], Ah[mf][3], q1, q3); \
                }                                                                       \
                _Pragma("unroll")                                                       \
                for (int mf = 0; mf < 2; mf++) {                                        \
                    mma16816(acc[mf][nf2 * 2 + 0], Al[mf][0], Al[mf][1], Al[mf][2], Al[mf][3], p0, p2); \
                    mma16816(acc[mf][nf2 * 2 + 1], Al[mf][0], Al[mf][1], Al[mf][2], Al[mf][3], p1, p3); \
                }                                                                       \
            }                                                                           \
        }                                                                               \
    }

// ---------------------------------------------------------------------------
// QKV projection (512 threads). tiles: [0,64) Q, [64,128) K, [128,384) V.
// ---------------------------------------------------------------------------
__global__ __launch_bounds__(512, 2)
void gemm_qkv(const bf16* __restrict__ Ahi, const bf16* __restrict__ Alo,
              const bf16* __restrict__ qwh, const bf16* __restrict__ qwl,
              const bf16* __restrict__ kwh, const bf16* __restrict__ kwl,
              const bf16* __restrict__ vwh, const bf16* __restrict__ vwl,
              bf16* __restrict__ qh, bf16* __restrict__ ql,
              bf16* __restrict__ kh, bf16* __restrict__ kl,
              bf16* __restrict__ vh, bf16* __restrict__ vl)
{
    int t = blockIdx.x;
    const bf16 *Bhi, *Blo;
    bf16 *Chi, *Clo;
    int N, bx, by;
    float cs;
    if (t < 64) {
        Bhi = qwh; Blo = qwl; Chi = qh; Clo = ql; N = 256; cs = 0.25f;
        bx = t & 1; by = t >> 1;
    } else if (t < 128) {
        t -= 64;
        Bhi = kwh; Blo = kwl; Chi = kh; Clo = kl; N = 256; cs = 1.f;
        bx = t & 1; by = t >> 1;
    } else {
        t -= 128;
        Bhi = vwh; Blo = vwl; Chi = vh; Clo = vl; N = 1024; cs = 1.f;
        bx = t & 7; by = t >> 3;
    }

    extern __shared__ char smem_raw[];
    const uint32_t sbase = smem_u32(smem_raw);

    const int tid = threadIdx.x;
    const int lane = tid & 31;
    const int warp = tid >> 5;
    const int wm = warp >> 2;   // 0..3
    const int wn = warp & 3;    // 0..3
    const int rowBase = by * 128;
    const int colBase = bx * 128;

    float acc[2][4][4];
#pragma unroll
    for (int i = 0; i < 2; i++)
#pragma unroll
        for (int j = 0; j < 4; j++)
#pragma unroll
            for (int e = 0; e < 4; e++) acc[i][j][e] = 0.f;

    const int lrow = lane & 15;
    const int lkb = ((lane >> 4) & 1) * 16;

    GEMM_MAINLOOP();

    const int r0b = rowBase + wm * 32 + (lane >> 2);
    const int c0b = colBase + wn * 32 + (lane & 3) * 2;
#pragma unroll
    for (int mf = 0; mf < 2; mf++) {
#pragma unroll
        for (int nf = 0; nf < 4; nf++) {
            int r = r0b + mf * 16;
            int c = c0b + nf * 8;
            float a0 = acc[mf][nf][0] * cs, a1 = acc[mf][nf][1] * cs;
            float a2 = acc[mf][nf][2] * cs, a3 = acc[mf][nf][3] * cs;
            uint32_t h01 = packbf(a0, a1);
            uint32_t h23 = packbf(a2, a3);
            uint32_t l01 = packbf(a0 - bflo(h01), a1 - bfhi(h01));
            uint32_t l23 = packbf(a2 - bflo(h23), a3 - bfhi(h23));
            ((uint32_t*)Chi)[((size_t)r * N + c) >> 1] = h01;
            ((uint32_t*)Clo)[((size_t)r * N + c) >> 1] = l01;
            ((uint32_t*)Chi)[((size_t)(r + 8) * N + c) >> 1] = h23;
            ((uint32_t*)Clo)[((size_t)(r + 8) * N + c) >> 1] = l23;
        }
    }
}

// ---------------------------------------------------------------------------
// O projection (512 threads): fp32 output.
// ---------------------------------------------------------------------------
__global__ __launch_bounds__(512, 2)
void gemm_out(const bf16* __restrict__ Ahi, const bf16* __restrict__ Alo,
              const bf16* __restrict__ Bhi, const bf16* __restrict__ Blo,
              float* __restrict__ C)
{
    extern __shared__ char smem_raw[];
    const uint32_t sbase = smem_u32(smem_raw);

    const int tid = threadIdx.x;
    const int lane = tid & 31;
    const int warp = tid >> 5;
    const int wm = warp >> 2;
    const int wn = warp & 3;
    const int rowBase = blockIdx.y * 128;
    const int colBase = blockIdx.x * 128;
    const int N = 1024;

    float acc[2][4][4];
#pragma unroll
    for (int i = 0; i < 2; i++)
#pragma unroll
        for (int j = 0; j < 4; j++)
#pragma unroll
            for (int e = 0; e < 4; e++) acc[i][j][e] = 0.f;

    const int lrow = lane & 15;
    const int lkb = ((lane >> 4) & 1) * 16;

    GEMM_MAINLOOP();

    const int r0b = rowBase + wm * 32 + (lane >> 2);
    const int c0b = colBase + wn * 32 + (lane & 3) * 2;
#pragma unroll
    for (int mf = 0; mf < 2; mf++) {
#pragma unroll
        for (int nf = 0; nf < 4; nf++) {
            int r = r0b + mf * 16;
            int c = c0b + nf * 8;
            *(float2*)&C[(size_t)r * N + c] = make_float2(acc[mf][nf][0], acc[mf][nf][1]);
            *(float2*)&C[(size_t)(r + 8) * N + c] = make_float2(acc[mf][nf][2], acc[mf][nf][3]);
        }
    }
}

// ---------------------------------------------------------------------------
// Attention: round-11 (paired query tiles; 128-key loads, 1 sync/load).
// ---------------------------------------------------------------------------
#define SQH 0
#define SQL 6144
#define S_TILES 12288
#define A_BUFSZ 49152
#define ATT_SMEM (S_TILES + 2 * A_BUFSZ)
#define SZOFF 33792
#define OSM_STRIDE 66

__global__ __launch_bounds__(256, 2)
void attn_mma(const bf16* __restrict__ qhi, const bf16* __restrict__ qlo,
              const bf16* __restrict__ khi, const bf16* __restrict__ klo,
              const bf16* __restrict__ vhi, const bf16* __restrict__ vlo,
              bf16* __restrict__ ohi, bf16* __restrict__ olo)
{
    extern __shared__ char smem_raw[];
    const uint32_t sbase = smem_u32(smem_raw);

    const int pr = blockIdx.x;
    const int h = blockIdx.y;
    const int b = blockIdx.z;

    const int tid = threadIdx.x;
    const int lane = tid & 31;
    const int warp = tid >> 5;
    const int wm = warp >> 1;
    const int wn = warp & 1;
    const int lrow = lane & 15;
    const int lkb = ((lane >> 4) & 1) * 16;
    const int lm = lane >> 3;
    const int lr = lane & 7;

#define ATT_LOAD128(t, bsel)                                                             \
    do {                                                                                 \
        const int j0_ = (t) * 128;                                                       \
        const uint32_t bb = sbase + S_TILES + (bsel) * A_BUFSZ;                          \
        _Pragma("unroll")                                                                \
        for (int t2 = 0; t2 < 2; t2++) {                                                 \
            int idx = t2 * 256 + tid;                                                    \
            int arr = idx >> 8;                                                          \
            int rem = idx & 255;                                                         \
            int row = rem >> 1;                                                          \
            int ch = rem & 1;                                                            \
            const bf16* src = arr ? klo : khi;                                           \
            cp_async16(bb + arr * 6144 + row * 48 + ch * 16,                             \
                       src + (size_t)(b * Ll + j0_ + row) * 256 + h * 16 + ch * 8);      \
        }                                                                                \
        _Pragma("unroll")                                                                \
        for (int t2 = 0; t2 < 8; t2++) {                                                 \
            int idx = t2 * 256 + tid;                                                    \
            int arr = idx >> 10;                                                         \
            int rem = idx & 1023;                                                        \
            int row = rem >> 3;                                                          \
            int ch = rem & 7;                                                            \
            const bf16* src = arr ? vlo : vhi;                                           \
            cp_async16(bb + 12288 + arr * 18432 + row * 144 + ch * 16,                   \
                       src + (size_t)(b * Ll + j0_ + row) * 1024 + h * 64 + ch * 8);     \
        }                                                                                \
        cp_commit();                                                                     \
    } while (0)

    for (int half = 0; half < 2; half++) {
        const int qt = (half == 0) ? (15 - pr) : pr;
        const int qi0 = qt * 128;
        const int nt = qt + 1;

#pragma unroll
        for (int t = 0; t < 2; t++) {
            int idx = t * 256 + tid;
            int arr = idx >> 8;
            int rem = idx & 255;
            int row = rem >> 1;
            int ch = rem & 1;
            const bf16* src = arr ? qlo : qhi;
            uint4 v = *(const uint4*)&src[(size_t)(b * Ll + qi0 + row) * 256 + h * 16 + ch * 8];
            *(uint4*)(smem_raw + (arr ? SQL : SQH) + row * 48 + ch * 16) = v;
        }
        ATT_LOAD128(0, 0);
        __syncthreads();

        uint32_t Aqh[2][4], Aql[2][4];
#pragma unroll
        for (int mf = 0; mf < 2; mf++) {
            uint32_t ra = sbase + SQH + (uint32_t)((wm * 32 + mf * 16 + lrow) * 48) + lkb;
            ldsm_x4(Aqh[mf][0], Aqh[mf][1], Aqh[mf][2], Aqh[mf][3], ra);
            ldsm_x4(Aql[mf][0], Aql[mf][1], Aql[mf][2], Aql[mf][3], ra + (SQL - SQH));
        }

        float oacc[2][8][4];
#pragma unroll
        for (int i = 0; i < 2; i++)
#pragma unroll
            for (int j = 0; j < 8; j++)
#pragma unroll
                for (int e = 0; e < 4; e++) oacc[i][j][e] = 0.f;
        float zv[2][2] = {{0.f, 0.f}, {0.f, 0.f}};

        for (int t = 0; t < nt; t++) {
            cp_wait0();
            __syncthreads();
            if (t + 1 < nt) ATT_LOAD128(t + 1, (t + 1) & 1);

            const uint32_t bb = sbase + S_TILES + (t & 1) * A_BUFSZ;

#pragma unroll
            for (int sub = 0; sub < 2; sub++) {
                const int j0 = t * 128 + sub * 64;
                const uint32_t kb = bb + (uint32_t)sub * 3072;
                const uint32_t vb = bb + 12288 + (uint32_t)sub * 9216;

                float sacc[2][4][4];
#pragma unroll
                for (int i = 0; i < 2; i++)
#pragma unroll
                    for (int j = 0; j < 4; j++)
#pragma unroll
                        for (int e = 0; e < 4; e++) sacc[i][j][e] = 0.f;

#pragma unroll
                for (int nf2 = 0; nf2 < 2; nf2++) {
                    uint32_t ra = kb + (uint32_t)((wn * 32 + nf2 * 16 + lrow) * 48) + lkb;
                    uint32_t kh0, kh1, kh2, kh3, kl0, kl1, kl2, kl3;
                    ldsm_x4(kh0, kh1, kh2, kh3, ra);
                    ldsm_x4(kl0, kl1, kl2, kl3, ra + 6144);
#pragma unroll
                    for (int mf = 0; mf < 2; mf++) {
                        mma16816(sacc[mf][nf2 * 2 + 0], Aqh[mf][0], Aqh[mf][1], Aqh[mf][2], Aqh[mf][3], kh0, kh2);
                        mma16816(sacc[mf][nf2 * 2 + 1], Aqh[mf][0], Aqh[mf][1], Aqh[mf][2], Aqh[mf][3], kh1, kh3);
                    }
#pragma unroll
                    for (int mf = 0; mf < 2; mf++) {
                        mma16816(sacc[mf][nf2 * 2 + 0], Aqh[mf][0], Aqh[mf][1], Aqh[mf][2], Aqh[mf][3], kl0, kl2);
                        mma16816(sacc[mf][nf2 * 2 + 1], Aqh[mf][0], Aqh[mf][1], Aqh[mf][2], Aqh[mf][3], kl1, kl3);
                    }
#pragma unroll
                    for (int mf = 0; mf < 2; mf++) {
                        mma16816(sacc[mf][nf2 * 2 + 0], Aql[mf][0], Aql[mf][1], Aql[mf][2], Aql[mf][3], kh0, kh2);
                        mma16816(sacc[mf][nf2 * 2 + 1], Aql[mf][0], Aql[mf][1], Aql[mf][2], Aql[mf][3], kh1, kh3);
                    }
                }

                if (j0 + 64 > qi0) {
                    const int rq = qi0 + wm * 32 + (lane >> 2);
                    const int cb0 = j0 + wn * 32 + (lane & 3) * 2;
#pragma unroll
                    for (int mf = 0; mf < 2; mf++) {
                        const int r0 = rq + mf * 16;
                        const int r1 = r0 + 8;
#pragma unroll
                        for (int nf = 0; nf < 4; nf++) {
                            float* c = sacc[mf][nf];
                            const int cb = cb0 + nf * 8;
                            if (cb > r0) c[0] = 0.f;
                            if (cb + 1 > r0) c[1] = 0.f;
                            if (cb > r1) c[2] = 0.f;
                            if (cb + 1 > r1) c[3] = 0.f;
                        }
                    }
                }

                uint32_t Ash[2][2][4], Asl[2][2][4];
#pragma unroll
                for (int mf = 0; mf < 2; mf++) {
#pragma unroll
                    for (int nf = 0; nf < 4; nf++) {
                        float* c = sacc[mf][nf];
                        float s0 = c[0] * c[0];
                        float s1 = c[1] * c[1];
                        float s2 = c[2] * c[2];
                        float s3 = c[3] * c[3];
                        zv[mf][0] += s0 + s1;
                        zv[mf][1] += s2 + s3;
                        uint32_t h01 = packbf(s0, s1);
                        uint32_t h23 = packbf(s2, s3);
                        uint32_t l01 = packbf(s0 - bflo(h01), s1 - bfhi(h01));
                        uint32_t l23 = packbf(s2 - bflo(h23), s3 - bfhi(h23));
                        int kc = nf >> 1, nfs = nf & 1;
                        Ash[mf][kc][nfs * 2 + 0] = h01;
                        Ash[mf][kc][nfs * 2 + 1] = h23;
                        Asl[mf][kc][nfs * 2 + 0] = l01;
                        Asl[mf][kc][nfs * 2 + 1] = l23;
                    }
                }

#pragma unroll
                for (int kc = 0; kc < 2; kc++) {
#pragma unroll
                    for (int nf2 = 0; nf2 < 4; nf2++) {
                        uint32_t av = vb +
                                      (uint32_t)((wn * 32 + kc * 16 + (lm & 1) * 8 + lr) * 144) +
                                      (uint32_t)(nf2 * 32 + (lm >> 1) * 16);
                        uint32_t vh0, vh1, vh2, vh3, vl0, vl1, vl2, vl3;
                        ldsm_x4_t(vh0, vh1, vh2, vh3, av);
                        ldsm_x4_t(vl0, vl1, vl2, vl3, av + 18432);
#pragma unroll
                        for (int mf = 0; mf < 2; mf++) {
                            mma16816(oacc[mf][nf2 * 2 + 0], Ash[mf][kc][0], Ash[mf][kc][1], Ash[mf][kc][2], Ash[mf][kc][3], vh0, vh1);
                            mma16816(oacc[mf][nf2 * 2 + 1], Ash[mf][kc][0], Ash[mf][kc][1], Ash[mf][kc][2], Ash[mf][kc][3], vh2, vh3);
                        }
#pragma unroll
                        for (int mf = 0; mf < 2; mf++) {
                            mma16816(oacc[mf][nf2 * 2 + 0], Ash[mf][kc][0], Ash[mf][kc][1], Ash[mf][kc][2], Ash[mf][kc][3], vl0, vl1);
                            mma16816(oacc[mf][nf2 * 2 + 1], Ash[mf][kc][0], Ash[mf][kc][1], Ash[mf][kc][2], Ash[mf][kc][3], vl2, vl3);
                        }
#pragma unroll
                        for (int mf = 0; mf < 2; mf++) {
                            mma16816(oacc[mf][nf2 * 2 + 0], Asl[mf][kc][0], Asl[mf][kc][1], Asl[mf][kc][2], Asl[mf][kc][3], vh0, vh1);
                            mma16816(oacc[mf][nf2 * 2 + 1], Asl[mf][kc][0], Asl[mf][kc][1], Asl[mf][kc][2], Asl[mf][kc][3], vh2, vh3);
                        }
                    }
                }
            }
        }
        __syncthreads();

#pragma unroll
        for (int mf = 0; mf < 2; mf++)
#pragma unroll
            for (int hf = 0; hf < 2; hf++) {
                zv[mf][hf] += __shfl_xor_sync(0xffffffffu, zv[mf][hf], 1);
                zv[mf][hf] += __shfl_xor_sync(0xffffffffu, zv[mf][hf], 2);
            }

        float* osm = (float*)smem_raw;
        float* zsm = (float*)(smem_raw + SZOFF);

        if (wn == 0) {
#pragma unroll
            for (int mf = 0; mf < 2; mf++) {
                int r0 = wm * 32 + mf * 16 + (lane >> 2);
#pragma unroll
                for (int nf = 0; nf < 8; nf++) {
                    int col = nf * 8 + (lane & 3) * 2;
                    *(float2*)&osm[r0 * OSM_STRIDE + col] = make_float2(oacc[mf][nf][0], oacc[mf][nf][1]);
                    *(float2*)&osm[(r0 + 8) * OSM_STRIDE + col] = make_float2(oacc[mf][nf][2], oacc[mf][nf][3]);
                }
                if ((lane & 3) == 0) {
                    zsm[r0] = zv[mf][0];
                    zsm[r0 + 8] = zv[mf][1];
                }
            }
        }
        __syncthreads();
        if (wn == 1) {
#pragma unroll
            for (int mf = 0; mf < 2; mf++) {
                int r0 = wm * 32 + mf * 16 + (lane >> 2);
                float inv0 = 1.f / (zv[mf][0] + zsm[r0] + 1e-5f);
                float inv1 = 1.f / (zv[mf][1] + zsm[r0 + 8] + 1e-5f);
                size_t g0 = (size_t)(b * Ll + qi0 + r0) * 1024 + h * 64;
                size_t g1 = (size_t)(b * Ll + qi0 + r0 + 8) * 1024 + h * 64;
#pragma unroll
                for (int nf = 0; nf < 8; nf++) {
                    int col = nf * 8 + (lane & 3) * 2;
                    float f0 = (oacc[mf][nf][0] + osm[r0 * OSM_STRIDE + col]) * inv0;
                    float f1 = (oacc[mf][nf][1] + osm[r0 * OSM_STRIDE + col + 1]) * inv0;
                    float f2 = (oacc[mf][nf][2] + osm[(r0 + 8) * OSM_STRIDE + col]) * inv1;
                    float f3 = (oacc[mf][nf][3] + osm[(r0 + 8) * OSM_STRIDE + col + 1]) * inv1;
                    uint32_t h01 = packbf(f0, f1);
                    uint32_t h23 = packbf(f2, f3);
                    uint32_t l01 = packbf(f0 - bflo(h01), f1 - bfhi(h01));
                    uint32_t l23 = packbf(f2 - bflo(h23), f3 - bfhi(h23));
                    ((uint32_t*)ohi)[(g0 + col) >> 1] = h01;
                    ((uint32_t*)olo)[(g0 + col) >> 1] = l01;
                    ((uint32_t*)ohi)[(g1 + col) >> 1] = h23;
                    ((uint32_t*)olo)[(g1 + col) >> 1] = l23;
                }
            }
        }
        __syncthreads();
    }
}

// ---------------------------------------------------------------------------
extern "C" void kernel_launch(void* const* d_in, const int* in_sizes, int n_in,
                              void* d_out, int out_size)
{
    const float* hidden = (const float*)d_in[0];
    const float* Wq = (const float*)d_in[1];
    const float* Wk = (const float*)d_in[2];
    const float* Wv = (const float*)d_in[3];
    const float* Wo = (const float*)d_in[4];
    float* out = (float*)d_out;

    bf16 *hhi, *hlo, *qhi, *qlo, *khi, *klo, *vhi, *vlo, *ohi, *olo;
    cudaGetSymbolAddress((void**)&hhi, g_hhi);
    cudaGetSymbolAddress((void**)&hlo, g_hlo);
    cudaGetSymbolAddress((void**)&qhi, g_qhi);
    cudaGetSymbolAddress((void**)&qlo, g_qlo);
    cudaGetSymbolAddress((void**)&khi, g_khi);
    cudaGetSymbolAddress((void**)&klo, g_klo);
    cudaGetSymbolAddress((void**)&vhi, g_vhi);
    cudaGetSymbolAddress((void**)&vlo, g_vlo);
    cudaGetSymbolAddress((void**)&ohi, g_ohi);
    cudaGetSymbolAddress((void**)&olo, g_olo);
    bf16 *wqh, *wql, *wkh, *wkl, *wvh, *wvl, *woh, *wol;
    cudaGetSymbolAddress((void**)&wqh, g_wqt_hi);
    cudaGetSymbolAddress((void**)&wql, g_wqt_lo);
    cudaGetSymbolAddress((void**)&wkh, g_wkt_hi);
    cudaGetSymbolAddress((void**)&wkl, g_wkt_lo);
    cudaGetSymbolAddress((void**)&wvh, g_wvt_hi);
    cudaGetSymbolAddress((void**)&wvl, g_wvt_lo);
    cudaGetSymbolAddress((void**)&woh, g_wot_hi);
    cudaGetSymbolAddress((void**)&wol, g_wot_lo);

    cudaFuncSetAttribute(gemm_qkv, cudaFuncAttributeMaxDynamicSharedMemorySize, GEMM_SMEM);
    cudaFuncSetAttribute(gemm_out, cudaFuncAttributeMaxDynamicSharedMemorySize, GEMM_SMEM);
    cudaFuncSetAttribute(attn_mma, cudaFuncAttributeMaxDynamicSharedMemorySize, ATT_SMEM);

    convert_all<<<dim3(32, 32, 5), dim3(32, 8)>>>(hidden, Wq, Wk, Wv, Wo,
        hhi, hlo, wqh, wql, wkh, wkl, wvh, wvl, woh, wol);

    gemm_qkv<<<384, 512, GEMM_SMEM>>>(hhi, hlo, wqh, wql, wkh, wkl, wvh, wvl,
                                      qhi, qlo, khi, klo, vhi, vlo);
    attn_mma<<<dim3(8, Hh, Bb), 256, ATT_SMEM>>>(qhi, qlo, khi, klo, vhi, vlo, ohi, olo);
    gemm_out<<<dim3(8, 32), 512, GEMM_SMEM>>>(ohi, olo, woh, wol, out);
}

// round 13
// speedup vs baseline: 1.2696x; 1.2696x over previous
#include <cuda_runtime.h>
#include <cuda_fp16.h>
#include <stdint.h>

// ReBasedLinearAttention: B=2, L=2048, D=1024, H=16, FD=16, HD=64
// fp16 mma.sync. Precision plan:
//   Q/K proj + QK^T : 3-MMA hi/lo x hi/lo  (squaring doubles error -> keep tight)
//   V proj, SV, Out : 2-MMA (A hi/lo exact, B single fp16; error = B trunc ~2^-12)
// Structure = round-11 champion (128x128 GEMM occ2 1-sync; paired-tile attention).

#define Bb 2
#define Ll 2048
#define Dd 1024
#define Hh 16
#define BL (Bb * Ll)

typedef unsigned long long ull;
typedef __half fp16;

// ---------------- scratch ----------------
__device__ fp16 g_hhi[BL * 1024];
__device__ fp16 g_hlo[BL * 1024];
__device__ fp16 g_qhi[BL * 256];
__device__ fp16 g_qlo[BL * 256];
__device__ fp16 g_khi[BL * 256];
__device__ fp16 g_klo[BL * 256];
__device__ fp16 g_v[BL * 1024];          // single fp16
__device__ fp16 g_ohi[BL * 1024];
__device__ fp16 g_olo[BL * 1024];

__device__ fp16 g_wqt_hi[256 * 1024];
__device__ fp16 g_wqt_lo[256 * 1024];
__device__ fp16 g_wkt_hi[256 * 1024];
__device__ fp16 g_wkt_lo[256 * 1024];
__device__ fp16 g_wvt[1024 * 1024];      // single fp16
__device__ fp16 g_wot[1024 * 1024];      // single fp16

// ---------------- PTX helpers ----------------
__device__ __forceinline__ uint32_t smem_u32(const void* p) {
    uint32_t a;
    asm("{ .reg .u64 t; cvta.to.shared.u64 t, %1; cvt.u32.u64 %0, t; }" : "=r"(a) : "l"(p));
    return a;
}
__device__ __forceinline__ void cp_async16(uint32_t saddr, const void* gaddr) {
    asm volatile("cp.async.cg.shared.global [%0], [%1], 16;" :: "r"(saddr), "l"(gaddr) : "memory");
}
__device__ __forceinline__ void cp_commit() {
    asm volatile("cp.async.commit_group;" ::: "memory");
}
__device__ __forceinline__ void cp_wait0() {
    asm volatile("cp.async.wait_group 0;" ::: "memory");
}
__device__ __forceinline__ void ldsm_x4(uint32_t& r0, uint32_t& r1, uint32_t& r2, uint32_t& r3,
                                        uint32_t addr) {
    asm volatile("ldmatrix.sync.aligned.m8n8.x4.shared.b16 {%0,%1,%2,%3}, [%4];"
                 : "=r"(r0), "=r"(r1), "=r"(r2), "=r"(r3) : "r"(addr));
}
__device__ __forceinline__ void ldsm_x4_t(uint32_t& r0, uint32_t& r1, uint32_t& r2, uint32_t& r3,
                                          uint32_t addr) {
    asm volatile("ldmatrix.sync.aligned.m8n8.x4.trans.shared.b16 {%0,%1,%2,%3}, [%4];"
                 : "=r"(r0), "=r"(r1), "=r"(r2), "=r"(r3) : "r"(addr));
}
__device__ __forceinline__ void mma16816(float c[4], uint32_t a0, uint32_t a1, uint32_t a2,
                                         uint32_t a3, uint32_t b0, uint32_t b1) {
    asm volatile(
        "mma.sync.aligned.m16n8k16.row.col.f32.f16.f16.f32 "
        "{%0,%1,%2,%3}, {%4,%5,%6,%7}, {%8,%9}, {%0,%1,%2,%3};"
        : "+f"(c[0]), "+f"(c[1]), "+f"(c[2]), "+f"(c[3])
        : "r"(a0), "r"(a1), "r"(a2), "r"(a3), "r"(b0), "r"(b1));
}
__device__ __forceinline__ uint32_t packh2(fp16 lo, fp16 hi) {
    __half2 t = __halves2half2(lo, hi);
    return *reinterpret_cast<uint32_t*>(&t);
}
// split x -> (h, l) with h + l == x to ~2^-24
__device__ __forceinline__ void spl(float x, fp16& h, fp16& l) {
    h = __float2half_rn(x);
    l = __float2half_rn(x - __half2float(h));
}

// ---------------------------------------------------------------------------
// Conversions: z 0=Wq(hi/lo) 1=Wk(hi/lo) 2=Wv(single) 3=Wo(single) 4=hidden split
// ---------------------------------------------------------------------------
__global__ void convert_all(const float* __restrict__ hidden,
                            const float* __restrict__ Wq, const float* __restrict__ Wk,
                            const float* __restrict__ Wv, const float* __restrict__ Wo,
                            fp16* __restrict__ hh, fp16* __restrict__ hl,
                            fp16* __restrict__ qh, fp16* __restrict__ ql,
                            fp16* __restrict__ kh, fp16* __restrict__ kl,
                            fp16* __restrict__ vt, fp16* __restrict__ ot)
{
    const int z = blockIdx.z;
    const int tid = threadIdx.y * 32 + threadIdx.x;
    if (z == 4) {
        int base = (blockIdx.y * (int)gridDim.x + blockIdx.x) * 1024 + tid * 4;
#pragma unroll
        for (int u = 0; u < 4; u++) {
            int i = base + u;
            float4 v = ((const float4*)hidden)[i];
            float vv[4] = {v.x, v.y, v.z, v.w};
            fp16 hhv[4], llv[4];
#pragma unroll
            for (int j = 0; j < 4; j++) spl(vv[j], hhv[j], llv[j]);
            *(ull*)&hh[(size_t)i * 4] = *(ull*)hhv;
            *(ull*)&hl[(size_t)i * 4] = *(ull*)llv;
        }
        return;
    }
    const int N = (z < 2) ? 256 : 1024;
    if (blockIdx.x * 32 >= N) return;
    const float* W = (z == 0) ? Wq : (z == 1) ? Wk : (z == 2) ? Wv : Wo;

    __shared__ float t[32][33];
    int n0 = blockIdx.x * 32, k0 = blockIdx.y * 32;
    int tx = threadIdx.x, ty = threadIdx.y;
#pragma unroll
    for (int i = 0; i < 4; i++)
        t[ty + i * 8][tx] = W[(size_t)(k0 + ty + i * 8) * N + n0 + tx];
    __syncthreads();
    if (z < 2) {
        fp16* thi = (z == 0) ? qh : kh;
        fp16* tlo = (z == 0) ? ql : kl;
#pragma unroll
        for (int i = 0; i < 4; i++) {
            int r = ty + i * 8;
            fp16 h, l;
            spl(t[tx][r], h, l);
            thi[(size_t)(n0 + r) * 1024 + k0 + tx] = h;
            tlo[(size_t)(n0 + r) * 1024 + k0 + tx] = l;
        }
    } else {
        fp16* ts = (z == 2) ? vt : ot;
#pragma unroll
        for (int i = 0; i < 4; i++) {
            int r = ty + i * 8;
            ts[(size_t)(n0 + r) * 1024 + k0 + tx] = __float2half_rn(t[tx][r]);
        }
    }
}

// ---------------------------------------------------------------------------
// GEMM cores: 128x128 tile, 256 threads (2m x 4n), BK=32, 1 sync/stage, occ 2.
// ---------------------------------------------------------------------------
#define ROWB 80
#define MATB (128 * ROWB)
#define STAGEB3 (4 * MATB)
#define GEMM3_SMEM (2 * STAGEB3)
#define STAGEB2 (3 * MATB)
#define GEMM2_SMEM (2 * STAGEB2)

// ---- 3-term (A hi/lo x B hi/lo, drop Al*Bl) ----
#define LOAD_STAGE3(s, buf)                                                             \
    do {                                                                                \
        const int k0 = (s) * 32;                                                        \
        const uint32_t sb_ = sbase + (buf) * STAGEB3;                                   \
        _Pragma("unroll")                                                               \
        for (int t = 0; t < 8; t++) {                                                   \
            int mat = t >> 1;                                                           \
            int sub = (t & 1) * 256 + tid;                                              \
            int row = sub >> 2;                                                         \
            int kc = sub & 3;                                                           \
            const fp16* src = (mat == 0) ? Ahi : (mat == 1) ? Alo                       \
                             : (mat == 2) ? Bhi : Blo;                                  \
            int grow = ((mat < 2) ? rowBase : colBase) + row;                           \
            cp_async16(sb_ + mat * MATB + row * ROWB + kc * 16,                         \
                       src + (size_t)grow * 1024 + k0 + kc * 8);                        \
        }                                                                               \
        cp_commit();                                                                    \
    } while (0)

#define GEMM_MAINLOOP3()                                                                \
    LOAD_STAGE3(0, 0);                                                                  \
    for (int s = 0; s < 32; s++) {                                                      \
        cp_wait0();                                                                     \
        __syncthreads();                                                                \
        if (s + 1 < 32) LOAD_STAGE3(s + 1, (s + 1) & 1);                                \
        const uint32_t sb = sbase + (s & 1) * STAGEB3;                                  \
        _Pragma("unroll")                                                               \
        for (int s2 = 0; s2 < 2; s2++) {                                                \
            const uint32_t kbyte = s2 * 32 + lkb;                                       \
            uint32_t Ah[4][4], Al[4][4];                                                \
            _Pragma("unroll")                                                           \
            for (int mf = 0; mf < 4; mf++) {                                            \
                uint32_t ra = sb + (uint32_t)((wm * 64 + mf * 16 + lrow) * ROWB) + kbyte; \
                ldsm_x4(Ah[mf][0], Ah[mf][1], Ah[mf][2], Ah[mf][3], ra);                \
                ldsm_x4(Al[mf][0], Al[mf][1], Al[mf][2], Al[mf][3], ra + MATB);         \
            }                                                                           \
            uint32_t Bh[4][2], Blr[4][2];                                               \
            _Pragma("unroll")                                                           \
            for (int nf2 = 0; nf2 < 2; nf2++) {                                         \
                uint32_t rb = sb + 2 * MATB +                                           \
                              (uint32_t)((wn * 32 + nf2 * 16 + lrow) * ROWB) + kbyte;   \
                uint32_t q0, q1, q2, q3;                                                \
                ldsm_x4(q0, q1, q2, q3, rb);                                            \
                Bh[nf2 * 2 + 0][0] = q0; Bh[nf2 * 2 + 0][1] = q2;                       \
                Bh[nf2 * 2 + 1][0] = q1; Bh[nf2 * 2 + 1][1] = q3;                       \
                ldsm_x4(q0, q1, q2, q3, rb + MATB);                                     \
                Blr[nf2 * 2 + 0][0] = q0; Blr[nf2 * 2 + 0][1] = q2;                     \
                Blr[nf2 * 2 + 1][0] = q1; Blr[nf2 * 2 + 1][1] = q3;                     \
            }                                                                           \
            _Pragma("unroll")                                                           \
            for (int mf = 0; mf < 4; mf++)                                              \
                _Pragma("unroll")                                                       \
                for (int nf = 0; nf < 4; nf++) {                                        \
                    mma16816(acc[mf][nf], Ah[mf][0], Ah[mf][1], Ah[mf][2], Ah[mf][3],   \
                             Bh[nf][0], Bh[nf][1]);                                     \
                    mma16816(acc[mf][nf], Ah[mf][0], Ah[mf][1], Ah[mf][2], Ah[mf][3],   \
                             Blr[nf][0], Blr[nf][1]);                                   \
                    mma16816(acc[mf][nf], Al[mf][0], Al[mf][1], Al[mf][2], Al[mf][3],   \
                             Bh[nf][0], Bh[nf][1]);                                     \
                }                                                                       \
        }                                                                               \
    }

// ---- 2-term (A hi/lo x B single) ----
#define LOAD_STAGE2(s, buf)                                                             \
    do {                                                                                \
        const int k0 = (s) * 32;                                                        \
        const uint32_t sb_ = sbase + (buf) * STAGEB2;                                   \
        _Pragma("unroll")                                                               \
        for (int t = 0; t < 6; t++) {                                                   \
            int idx = t * 256 + tid;                                                    \
            int mat = idx >> 9;                                                         \
            int rem = idx & 511;                                                        \
            int row = rem >> 2;                                                         \
            int kc = rem & 3;                                                           \
            const fp16* src = (mat == 0) ? Ahi : (mat == 1) ? Alo : Bs;                 \
            int grow = ((mat < 2) ? rowBase : colBase) + row;                           \
            cp_async16(sb_ + mat * MATB + row * ROWB + kc * 16,                         \
                       src + (size_t)grow * 1024 + k0 + kc * 8);                        \
        }                                                                               \
        cp_commit();                                                                    \
    } while (0)

#define GEMM_MAINLOOP2()                                                                \
    LOAD_STAGE2(0, 0);                                                                  \
    for (int s = 0; s < 32; s++) {                                                      \
        cp_wait0();                                                                     \
        __syncthreads();                                                                \
        if (s + 1 < 32) LOAD_STAGE2(s + 1, (s + 1) & 1);                                \
        const uint32_t sb = sbase + (s & 1) * STAGEB2;                                  \
        _Pragma("unroll")                                                               \
        for (int s2 = 0; s2 < 2; s2++) {                                                \
            const uint32_t kbyte = s2 * 32 + lkb;                                       \
            uint32_t Ah[4][4], Al[4][4];                                                \
            _Pragma("unroll")                                                           \
            for (int mf = 0; mf < 4; mf++) {                                            \
                uint32_t ra = sb + (uint32_t)((wm * 64 + mf * 16 + lrow) * ROWB) + kbyte; \
                ldsm_x4(Ah[mf][0], Ah[mf][1], Ah[mf][2], Ah[mf][3], ra);                \
                ldsm_x4(Al[mf][0], Al[mf][1], Al[mf][2], Al[mf][3], ra + MATB);         \
            }                                                                           \
            uint32_t Bv[4][2];                                                          \
            _Pragma("unroll")                                                           \
            for (int nf2 = 0; nf2 < 2; nf2++) {                                         \
                uint32_t rb = sb + 2 * MATB +                                           \
                              (uint32_t)((wn * 32 + nf2 * 16 + lrow) * ROWB) + kbyte;   \
                uint32_t q0, q1, q2, q3;                                                \
                ldsm_x4(q0, q1, q2, q3, rb);                                            \
                Bv[nf2 * 2 + 0][0] = q0; Bv[nf2 * 2 + 0][1] = q2;                       \
                Bv[nf2 * 2 + 1][0] = q1; Bv[nf2 * 2 + 1][1] = q3;                       \
            }                                                                           \
            _Pragma("unroll")                                                           \
            for (int mf = 0; mf < 4; mf++)                                              \
                _Pragma("unroll")                                                       \
                for (int nf = 0; nf < 4; nf++) {                                        \
                    mma16816(acc[mf][nf], Ah[mf][0], Ah[mf][1], Ah[mf][2], Ah[mf][3],   \
                             Bv[nf][0], Bv[nf][1]);                                     \
                    mma16816(acc[mf][nf], Al[mf][0], Al[mf][1], Al[mf][2], Al[mf][3],   \
                             Bv[nf][0], Bv[nf][1]);                                     \
                }                                                                       \
        }                                                                               \
    }

// ---------------------------------------------------------------------------
// Q & K projections (3-term). tiles: [0,64) Q (x0.25), [64,128) K.
// ---------------------------------------------------------------------------
__global__ __launch_bounds__(256, 2)
void gemm_qk(const fp16* __restrict__ Ahi, const fp16* __restrict__ Alo,
             const fp16* __restrict__ qwh, const fp16* __restrict__ qwl,
             const fp16* __restrict__ kwh, const fp16* __restrict__ kwl,
             fp16* __restrict__ qh, fp16* __restrict__ ql,
             fp16* __restrict__ kh, fp16* __restrict__ kl)
{
    int t = blockIdx.x;
    const bool isQ = (t < 64);
    if (!isQ) t -= 64;
    const fp16* Bhi = isQ ? qwh : kwh;
    const fp16* Blo = isQ ? qwl : kwl;
    fp16* Chi = isQ ? qh : kh;
    fp16* Clo = isQ ? ql : kl;
    const float cs = isQ ? 0.25f : 1.f;
    const int N = 256;
    const int bx = t & 1, by = t >> 1;

    extern __shared__ char smem_raw[];
    const uint32_t sbase = smem_u32(smem_raw);

    const int tid = threadIdx.x;
    const int lane = tid & 31;
    const int warp = tid >> 5;
    const int wm = warp >> 2;
    const int wn = warp & 3;
    const int rowBase = by * 128;
    const int colBase = bx * 128;

    float acc[4][4][4];
#pragma unroll
    for (int i = 0; i < 4; i++)
#pragma unroll
        for (int j = 0; j < 4; j++)
#pragma unroll
            for (int e = 0; e < 4; e++) acc[i][j][e] = 0.f;

    const int lrow = lane & 15;
    const int lkb = ((lane >> 4) & 1) * 16;

    GEMM_MAINLOOP3();

    const int r0b = rowBase + wm * 64 + (lane >> 2);
    const int c0b = colBase + wn * 32 + (lane & 3) * 2;
#pragma unroll
    for (int mf = 0; mf < 4; mf++) {
#pragma unroll
        for (int nf = 0; nf < 4; nf++) {
            int r = r0b + mf * 16;
            int c = c0b + nf * 8;
            float a[4];
#pragma unroll
            for (int e = 0; e < 4; e++) a[e] = acc[mf][nf][e] * cs;
            fp16 h[4], l[4];
#pragma unroll
            for (int e = 0; e < 4; e++) spl(a[e], h[e], l[e]);
            ((uint32_t*)Chi)[((size_t)r * N + c) >> 1] = packh2(h[0], h[1]);
            ((uint32_t*)Clo)[((size_t)r * N + c) >> 1] = packh2(l[0], l[1]);
            ((uint32_t*)Chi)[((size_t)(r + 8) * N + c) >> 1] = packh2(h[2], h[3]);
            ((uint32_t*)Clo)[((size_t)(r + 8) * N + c) >> 1] = packh2(l[2], l[3]);
        }
    }
}

// ---------------------------------------------------------------------------
// V projection (2-term): v = h @ Wv (single fp16 out).
// ---------------------------------------------------------------------------
__global__ __launch_bounds__(256, 2)
void gemm_v(const fp16* __restrict__ Ahi, const fp16* __restrict__ Alo,
            const fp16* __restrict__ Bs, fp16* __restrict__ V)
{
    extern __shared__ char smem_raw[];
    const uint32_t sbase = smem_u32(smem_raw);

    const int tid = threadIdx.x;
    const int lane = tid & 31;
    const int warp = tid >> 5;
    const int wm = warp >> 2;
    const int wn = warp & 3;
    const int rowBase = blockIdx.y * 128;
    const int colBase = blockIdx.x * 128;
    const int N = 1024;

    float acc[4][4][4];
#pragma unroll
    for (int i = 0; i < 4; i++)
#pragma unroll
        for (int j = 0; j < 4; j++)
#pragma unroll
            for (int e = 0; e < 4; e++) acc[i][j][e] = 0.f;

    const int lrow = lane & 15;
    const int lkb = ((lane >> 4) & 1) * 16;

    GEMM_MAINLOOP2();

    const int r0b = rowBase + wm * 64 + (lane >> 2);
    const int c0b = colBase + wn * 32 + (lane & 3) * 2;
#pragma unroll
    for (int mf = 0; mf < 4; mf++) {
#pragma unroll
        for (int nf = 0; nf < 4; nf++) {
            int r = r0b + mf * 16;
            int c = c0b + nf * 8;
            ((uint32_t*)V)[((size_t)r * N + c) >> 1] =
                packh2(__float2half_rn(acc[mf][nf][0]), __float2half_rn(acc[mf][nf][1]));
            ((uint32_t*)V)[((size_t)(r + 8) * N + c) >> 1] =
                packh2(__float2half_rn(acc[mf][nf][2]), __float2half_rn(acc[mf][nf][3]));
        }
    }
}

// ---------------------------------------------------------------------------
// O projection (2-term): out = o @ Wo, fp32 out.
// ---------------------------------------------------------------------------
__global__ __launch_bounds__(256, 2)
void gemm_out(const fp16* __restrict__ Ahi, const fp16* __restrict__ Alo,
              const fp16* __restrict__ Bs, float* __restrict__ C)
{
    extern __shared__ char smem_raw[];
    const uint32_t sbase = smem_u32(smem_raw);

    const int tid = threadIdx.x;
    const int lane = tid & 31;
    const int warp = tid >> 5;
    const int wm = warp >> 2;
    const int wn = warp & 3;
    const int rowBase = blockIdx.y * 128;
    const int colBase = blockIdx.x * 128;
    const int N = 1024;

    float acc[4][4][4];
#pragma unroll
    for (int i = 0; i < 4; i++)
#pragma unroll
        for (int j = 0; j < 4; j++)
#pragma unroll
            for (int e = 0; e < 4; e++) acc[i][j][e] = 0.f;

    const int lrow = lane & 15;
    const int lkb = ((lane >> 4) & 1) * 16;

    GEMM_MAINLOOP2();

    const int r0b = rowBase + wm * 64 + (lane >> 2);
    const int c0b = colBase + wn * 32 + (lane & 3) * 2;
#pragma unroll
    for (int mf = 0; mf < 4; mf++) {
#pragma unroll
        for (int nf = 0; nf < 4; nf++) {
            int r = r0b + mf * 16;
            int c = c0b + nf * 8;
            *(float2*)&C[(size_t)r * N + c] = make_float2(acc[mf][nf][0], acc[mf][nf][1]);
            *(float2*)&C[(size_t)(r + 8) * N + c] = make_float2(acc[mf][nf][2], acc[mf][nf][3]);
        }
    }
}

// ---------------------------------------------------------------------------
// Attention: paired query tiles; 128-key loads; QK 3-term, SV 2-term (v single).
// buffer: kh +0 (6144), kl +6144 (6144), v +12288 (18432)  => A_BUFSZ 30720
// ---------------------------------------------------------------------------
#define SQH 0
#define SQL 6144
#define S_TILES 12288
#define A_BUFSZ 30720
#define ATT_SMEM (S_TILES + 2 * A_BUFSZ)   // 73728
#define SZOFF 33792
#define OSM_STRIDE 66

__global__ __launch_bounds__(256, 2)
void attn_mma(const fp16* __restrict__ qhi, const fp16* __restrict__ qlo,
              const fp16* __restrict__ khi, const fp16* __restrict__ klo,
              const fp16* __restrict__ vv,
              fp16* __restrict__ ohi, fp16* __restrict__ olo)
{
    extern __shared__ char smem_raw[];
    const uint32_t sbase = smem_u32(smem_raw);

    const int pr = blockIdx.x;   // 0..7
    const int h = blockIdx.y;
    const int b = blockIdx.z;

    const int tid = threadIdx.x;
    const int lane = tid & 31;
    const int warp = tid >> 5;
    const int wm = warp >> 1;
    const int wn = warp & 1;
    const int lrow = lane & 15;
    const int lkb = ((lane >> 4) & 1) * 16;
    const int lm = lane >> 3;
    const int lr = lane & 7;

#define ATT_LOAD128(t, bsel)                                                             \
    do {                                                                                 \
        const int j0_ = (t) * 128;                                                       \
        const uint32_t bb = sbase + S_TILES + (bsel) * A_BUFSZ;                          \
        _Pragma("unroll")                                                                \
        for (int t2 = 0; t2 < 2; t2++) {                                                 \
            int idx = t2 * 256 + tid;                                                    \
            int arr = idx >> 8;                                                          \
            int rem = idx & 255;                                                         \
            int row = rem >> 1;                                                          \
            int ch = rem & 1;                                                            \
            const fp16* src = arr ? klo : khi;                                           \
            cp_async16(bb + arr * 6144 + row * 48 + ch * 16,                             \
                       src + (size_t)(b * Ll + j0_ + row) * 256 + h * 16 + ch * 8);      \
        }                                                                                \
        _Pragma("unroll")                                                                \
        for (int t2 = 0; t2 < 4; t2++) {                                                 \
            int idx = t2 * 256 + tid;                                                    \
            int row = idx >> 3;                                                          \
            int ch = idx & 7;                                                            \
            cp_async16(bb + 12288 + row * 144 + ch * 16,                                 \
                       vv + (size_t)(b * Ll + j0_ + row) * 1024 + h * 64 + ch * 8);      \
        }                                                                                \
        cp_commit();                                                                     \
    } while (0)

    for (int half = 0; half < 2; half++) {
        const int qt = (half == 0) ? (15 - pr) : pr;
        const int qi0 = qt * 128;
        const int nt = qt + 1;

#pragma unroll
        for (int t = 0; t < 2; t++) {
            int idx = t * 256 + tid;
            int arr = idx >> 8;
            int rem = idx & 255;
            int row = rem >> 1;
            int ch = rem & 1;
            const fp16* src = arr ? qlo : qhi;
            uint4 v = *(const uint4*)&src[(size_t)(b * Ll + qi0 + row) * 256 + h * 16 + ch * 8];
            *(uint4*)(smem_raw + (arr ? SQL : SQH) + row * 48 + ch * 16) = v;
        }
        ATT_LOAD128(0, 0);
        __syncthreads();

        uint32_t Aqh[2][4], Aql[2][4];
#pragma unroll
        for (int mf = 0; mf < 2; mf++) {
            uint32_t ra = sbase + SQH + (uint32_t)((wm * 32 + mf * 16 + lrow) * 48) + lkb;
            ldsm_x4(Aqh[mf][0], Aqh[mf][1], Aqh[mf][2], Aqh[mf][3], ra);
            ldsm_x4(Aql[mf][0], Aql[mf][1], Aql[mf][2], Aql[mf][3], ra + (SQL - SQH));
        }

        float oacc[2][8][4];
#pragma unroll
        for (int i = 0; i < 2; i++)
#pragma unroll
            for (int j = 0; j < 8; j++)
#pragma unroll
                for (int e = 0; e < 4; e++) oacc[i][j][e] = 0.f;
        float zv[2][2] = {{0.f, 0.f}, {0.f, 0.f}};

        for (int t = 0; t < nt; t++) {
            cp_wait0();
            __syncthreads();
            if (t + 1 < nt) ATT_LOAD128(t + 1, (t + 1) & 1);

            const uint32_t bb = sbase + S_TILES + (t & 1) * A_BUFSZ;

#pragma unroll
            for (int sub = 0; sub < 2; sub++) {
                const int j0 = t * 128 + sub * 64;
                const uint32_t kb = bb + (uint32_t)sub * 3072;
                const uint32_t vb = bb + 12288 + (uint32_t)sub * 9216;

                // ---- QK^T (3-term) ----
                float sacc[2][4][4];
#pragma unroll
                for (int i = 0; i < 2; i++)
#pragma unroll
                    for (int j = 0; j < 4; j++)
#pragma unroll
                        for (int e = 0; e < 4; e++) sacc[i][j][e] = 0.f;

#pragma unroll
                for (int nf2 = 0; nf2 < 2; nf2++) {
                    uint32_t ra = kb + (uint32_t)((wn * 32 + nf2 * 16 + lrow) * 48) + lkb;
                    uint32_t kh0, kh1, kh2, kh3, kl0, kl1, kl2, kl3;
                    ldsm_x4(kh0, kh1, kh2, kh3, ra);
                    ldsm_x4(kl0, kl1, kl2, kl3, ra + 6144);
#pragma unroll
                    for (int mf = 0; mf < 2; mf++) {
                        mma16816(sacc[mf][nf2 * 2 + 0], Aqh[mf][0], Aqh[mf][1], Aqh[mf][2], Aqh[mf][3], kh0, kh2);
                        mma16816(sacc[mf][nf2 * 2 + 1], Aqh[mf][0], Aqh[mf][1], Aqh[mf][2], Aqh[mf][3], kh1, kh3);
                    }
#pragma unroll
                    for (int mf = 0; mf < 2; mf++) {
                        mma16816(sacc[mf][nf2 * 2 + 0], Aqh[mf][0], Aqh[mf][1], Aqh[mf][2], Aqh[mf][3], kl0, kl2);
                        mma16816(sacc[mf][nf2 * 2 + 1], Aqh[mf][0], Aqh[mf][1], Aqh[mf][2], Aqh[mf][3], kl1, kl3);
                    }
#pragma unroll
                    for (int mf = 0; mf < 2; mf++) {
                        mma16816(sacc[mf][nf2 * 2 + 0], Aql[mf][0], Aql[mf][1], Aql[mf][2], Aql[mf][3], kh0, kh2);
                        mma16816(sacc[mf][nf2 * 2 + 1], Aql[mf][0], Aql[mf][1], Aql[mf][2], Aql[mf][3], kh1, kh3);
                    }
                }

                // ---- mask ----
                if (j0 + 64 > qi0) {
                    const int rq = qi0 + wm * 32 + (lane >> 2);
                    const int cb0 = j0 + wn * 32 + (lane & 3) * 2;
#pragma unroll
                    for (int mf = 0; mf < 2; mf++) {
                        const int r0 = rq + mf * 16;
                        const int r1 = r0 + 8;
#pragma unroll
                        for (int nf = 0; nf < 4; nf++) {
                            float* c = sacc[mf][nf];
                            const int cb = cb0 + nf * 8;
                            if (cb > r0) c[0] = 0.f;
                            if (cb + 1 > r0) c[1] = 0.f;
                            if (cb > r1) c[2] = 0.f;
                            if (cb + 1 > r1) c[3] = 0.f;
                        }
                    }
                }

                // ---- square, z, repack to fp16 hi/lo A-frags ----
                uint32_t Ash[2][2][4], Asl[2][2][4];
#pragma unroll
                for (int mf = 0; mf < 2; mf++) {
#pragma unroll
                    for (int nf = 0; nf < 4; nf++) {
                        float* c = sacc[mf][nf];
                        float s0 = c[0] * c[0];
                        float s1 = c[1] * c[1];
                        float s2 = c[2] * c[2];
                        float s3 = c[3] * c[3];
                        zv[mf][0] += s0 + s1;
                        zv[mf][1] += s2 + s3;
                        fp16 h0, l0, h1, l1, h2, l2, h3, l3;
                        spl(s0, h0, l0); spl(s1, h1, l1);
                        spl(s2, h2, l2); spl(s3, h3, l3);
                        int kc = nf >> 1, nfs = nf & 1;
                        Ash[mf][kc][nfs * 2 + 0] = packh2(h0, h1);
                        Ash[mf][kc][nfs * 2 + 1] = packh2(h2, h3);
                        Asl[mf][kc][nfs * 2 + 0] = packh2(l0, l1);
                        Asl[mf][kc][nfs * 2 + 1] = packh2(l2, l3);
                    }
                }

                // ---- SV (2-term: s hi/lo x v single) ----
#pragma unroll
                for (int kc = 0; kc < 2; kc++) {
#pragma unroll
                    for (int nf2 = 0; nf2 < 4; nf2++) {
                        uint32_t av = vb +
                                      (uint32_t)((wn * 32 + kc * 16 + (lm & 1) * 8 + lr) * 144) +
                                      (uint32_t)(nf2 * 32 + (lm >> 1) * 16);
                        uint32_t vh0, vh1, vh2, vh3;
                        ldsm_x4_t(vh0, vh1, vh2, vh3, av);
#pragma unroll
                        for (int mf = 0; mf < 2; mf++) {
                            mma16816(oacc[mf][nf2 * 2 + 0], Ash[mf][kc][0], Ash[mf][kc][1], Ash[mf][kc][2], Ash[mf][kc][3], vh0, vh1);
                            mma16816(oacc[mf][nf2 * 2 + 1], Ash[mf][kc][0], Ash[mf][kc][1], Ash[mf][kc][2], Ash[mf][kc][3], vh2, vh3);
                        }
#pragma unroll
                        for (int mf = 0; mf < 2; mf++) {
                            mma16816(oacc[mf][nf2 * 2 + 0], Asl[mf][kc][0], Asl[mf][kc][1], Asl[mf][kc][2], Asl[mf][kc][3], vh0, vh1);
                            mma16816(oacc[mf][nf2 * 2 + 1], Asl[mf][kc][0], Asl[mf][kc][1], Asl[mf][kc][2], Asl[mf][kc][3], vh2, vh3);
                        }
                    }
                }
            }
        }
        __syncthreads();

        // ---- epilogue ----
#pragma unroll
        for (int mf = 0; mf < 2; mf++)
#pragma unroll
            for (int hf = 0; hf < 2; hf++) {
                zv[mf][hf] += __shfl_xor_sync(0xffffffffu, zv[mf][hf], 1);
                zv[mf][hf] += __shfl_xor_sync(0xffffffffu, zv[mf][hf], 2);
            }

        float* osm = (float*)smem_raw;
        float* zsm = (float*)(smem_raw + SZOFF);

        if (wn == 0) {
#pragma unroll
            for (int mf = 0; mf < 2; mf++) {
                int r0 = wm * 32 + mf * 16 + (lane >> 2);
#pragma unroll
                for (int nf = 0; nf < 8; nf++) {
                    int col = nf * 8 + (lane & 3) * 2;
                    *(float2*)&osm[r0 * OSM_STRIDE + col] = make_float2(oacc[mf][nf][0], oacc[mf][nf][1]);
                    *(float2*)&osm[(r0 + 8) * OSM_STRIDE + col] = make_float2(oacc[mf][nf][2], oacc[mf][nf][3]);
                }
                if ((lane & 3) == 0) {
                    zsm[r0] = zv[mf][0];
                    zsm[r0 + 8] = zv[mf][1];
                }
            }
        }
        __syncthreads();
        if (wn == 1) {
#pragma unroll
            for (int mf = 0; mf < 2; mf++) {
                int r0 = wm * 32 + mf * 16 + (lane >> 2);
                float inv0 = 1.f / (zv[mf][0] + zsm[r0] + 1e-5f);
                float inv1 = 1.f / (zv[mf][1] + zsm[r0 + 8] + 1e-5f);
                size_t g0 = (size_t)(b * Ll + qi0 + r0) * 1024 + h * 64;
                size_t g1 = (size_t)(b * Ll + qi0 + r0 + 8) * 1024 + h * 64;
#pragma unroll
                for (int nf = 0; nf < 8; nf++) {
                    int col = nf * 8 + (lane & 3) * 2;
                    float f0 = (oacc[mf][nf][0] + osm[r0 * OSM_STRIDE + col]) * inv0;
                    float f1 = (oacc[mf][nf][1] + osm[r0 * OSM_STRIDE + col + 1]) * inv0;
                    float f2 = (oacc[mf][nf][2] + osm[(r0 + 8) * OSM_STRIDE + col]) * inv1;
                    float f3 = (oacc[mf][nf][3] + osm[(r0 + 8) * OSM_STRIDE + col + 1]) * inv1;
                    fp16 h0, l0, h1, l1, h2, l2, h3, l3;
                    spl(f0, h0, l0); spl(f1, h1, l1);
                    spl(f2, h2, l2); spl(f3, h3, l3);
                    ((uint32_t*)ohi)[(g0 + col) >> 1] = packh2(h0, h1);
                    ((uint32_t*)olo)[(g0 + col) >> 1] = packh2(l0, l1);
                    ((uint32_t*)ohi)[(g1 + col) >> 1] = packh2(h2, h3);
                    ((uint32_t*)olo)[(g1 + col) >> 1] = packh2(l2, l3);
                }
            }
        }
        __syncthreads();
    }
}

// ---------------------------------------------------------------------------
extern "C" void kernel_launch(void* const* d_in, const int* in_sizes, int n_in,
                              void* d_out, int out_size)
{
    const float* hidden = (const float*)d_in[0];
    const float* Wq = (const float*)d_in[1];
    const float* Wk = (const float*)d_in[2];
    const float* Wv = (const float*)d_in[3];
    const float* Wo = (const float*)d_in[4];
    float* out = (float*)d_out;

    fp16 *hhi, *hlo, *qhi, *qlo, *khi, *klo, *vv, *ohi, *olo;
    cudaGetSymbolAddress((void**)&hhi, g_hhi);
    cudaGetSymbolAddress((void**)&hlo, g_hlo);
    cudaGetSymbolAddress((void**)&qhi, g_qhi);
    cudaGetSymbolAddress((void**)&qlo, g_qlo);
    cudaGetSymbolAddress((void**)&khi, g_khi);
    cudaGetSymbolAddress((void**)&klo, g_klo);
    cudaGetSymbolAddress((void**)&vv, g_v);
    cudaGetSymbolAddress((void**)&ohi, g_ohi);
    cudaGetSymbolAddress((void**)&olo, g_olo);
    fp16 *wqh, *wql, *wkh, *wkl, *wvt, *wot;
    cudaGetSymbolAddress((void**)&wqh, g_wqt_hi);
    cudaGetSymbolAddress((void**)&wql, g_wqt_lo);
    cudaGetSymbolAddress((void**)&wkh, g_wkt_hi);
    cudaGetSymbolAddress((void**)&wkl, g_wkt_lo);
    cudaGetSymbolAddress((void**)&wvt, g_wvt);
    cudaGetSymbolAddress((void**)&wot, g_wot);

    cudaFuncSetAttribute(gemm_qk, cudaFuncAttributeMaxDynamicSharedMemorySize, GEMM3_SMEM);
    cudaFuncSetAttribute(gemm_v, cudaFuncAttributeMaxDynamicSharedMemorySize, GEMM2_SMEM);
    cudaFuncSetAttribute(gemm_out, cudaFuncAttributeMaxDynamicSharedMemorySize, GEMM2_SMEM);
    cudaFuncSetAttribute(attn_mma, cudaFuncAttributeMaxDynamicSharedMemorySize, ATT_SMEM);

    convert_all<<<dim3(32, 32, 5), dim3(32, 8)>>>(hidden, Wq, Wk, Wv, Wo,
        hhi, hlo, wqh, wql, wkh, wkl, wvt, wot);

    gemm_qk<<<128, 256, GEMM3_SMEM>>>(hhi, hlo, wqh, wql, wkh, wkl, qhi, qlo, khi, klo);
    gemm_v<<<dim3(8, 32), 256, GEMM2_SMEM>>>(hhi, hlo, wvt, vv);
    attn_mma<<<dim3(8, Hh, Bb), 256, ATT_SMEM>>>(qhi, qlo, khi, klo, vv, ohi, olo);
    gemm_out<<<dim3(8, 32), 256, GEMM2_SMEM>>>(ohi, olo, wot, out);
}

// round 14
// speedup vs baseline: 1.7809x; 1.4027x over previous
#include <cuda_runtime.h>
#include <cuda_fp16.h>
#include <stdint.h>

// ReBasedLinearAttention: B=2, L=2048, D=1024, H=16, FD=16, HD=64
// fp16 mma.sync. Precision plan (error budget vs 1e-3):
//   Q/K proj + QK^T : 3-MMA hi/lo x hi/lo (squared path, kept tight)
//   V proj          : 1-MMA (h single x Wv single)
//   SV              : 1-MMA (s single x v single); z exact fp32
//   Out proj        : 1-MMA (o single x Wo single)

#define Bb 2
#define Ll 2048
#define Dd 1024
#define Hh 16
#define BL (Bb * Ll)

typedef unsigned long long ull;
typedef __half fp16;

// ---------------- scratch ----------------
__device__ fp16 g_hhi[BL * 1024];
__device__ fp16 g_hlo[BL * 1024];
__device__ fp16 g_qhi[BL * 256];
__device__ fp16 g_qlo[BL * 256];
__device__ fp16 g_khi[BL * 256];
__device__ fp16 g_klo[BL * 256];
__device__ fp16 g_v[BL * 1024];
__device__ fp16 g_o[BL * 1024];

__device__ fp16 g_wqt_hi[256 * 1024];
__device__ fp16 g_wqt_lo[256 * 1024];
__device__ fp16 g_wkt_hi[256 * 1024];
__device__ fp16 g_wkt_lo[256 * 1024];
__device__ fp16 g_wvt[1024 * 1024];
__device__ fp16 g_wot[1024 * 1024];

// ---------------- PTX helpers ----------------
__device__ __forceinline__ uint32_t smem_u32(const void* p) {
    uint32_t a;
    asm("{ .reg .u64 t; cvta.to.shared.u64 t, %1; cvt.u32.u64 %0, t; }" : "=r"(a) : "l"(p));
    return a;
}
__device__ __forceinline__ void cp_async16(uint32_t saddr, const void* gaddr) {
    asm volatile("cp.async.cg.shared.global [%0], [%1], 16;" :: "r"(saddr), "l"(gaddr) : "memory");
}
__device__ __forceinline__ void cp_commit() {
    asm volatile("cp.async.commit_group;" ::: "memory");
}
__device__ __forceinline__ void cp_wait0() {
    asm volatile("cp.async.wait_group 0;" ::: "memory");
}
__device__ __forceinline__ void ldsm_x4(uint32_t& r0, uint32_t& r1, uint32_t& r2, uint32_t& r3,
                                        uint32_t addr) {
    asm volatile("ldmatrix.sync.aligned.m8n8.x4.shared.b16 {%0,%1,%2,%3}, [%4];"
                 : "=r"(r0), "=r"(r1), "=r"(r2), "=r"(r3) : "r"(addr));
}
__device__ __forceinline__ void ldsm_x4_t(uint32_t& r0, uint32_t& r1, uint32_t& r2, uint32_t& r3,
                                          uint32_t addr) {
    asm volatile("ldmatrix.sync.aligned.m8n8.x4.trans.shared.b16 {%0,%1,%2,%3}, [%4];"
                 : "=r"(r0), "=r"(r1), "=r"(r2), "=r"(r3) : "r"(addr));
}
__device__ __forceinline__ void mma16816(float c[4], uint32_t a0, uint32_t a1, uint32_t a2,
                                         uint32_t a3, uint32_t b0, uint32_t b1) {
    asm volatile(
        "mma.sync.aligned.m16n8k16.row.col.f32.f16.f16.f32 "
        "{%0,%1,%2,%3}, {%4,%5,%6,%7}, {%8,%9}, {%0,%1,%2,%3};"
        : "+f"(c[0]), "+f"(c[1]), "+f"(c[2]), "+f"(c[3])
        : "r"(a0), "r"(a1), "r"(a2), "r"(a3), "r"(b0), "r"(b1));
}
__device__ __forceinline__ uint32_t packh2(fp16 lo, fp16 hi) {
    __half2 t = __halves2half2(lo, hi);
    return *reinterpret_cast<uint32_t*>(&t);
}
__device__ __forceinline__ void spl(float x, fp16& h, fp16& l) {
    h = __float2half_rn(x);
    l = __float2half_rn(x - __half2float(h));
}

// ---------------------------------------------------------------------------
// Conversions: z 0=Wq(hi/lo) 1=Wk(hi/lo) 2=Wv(single) 3=Wo(single) 4=hidden split
// ---------------------------------------------------------------------------
__global__ void convert_all(const float* __restrict__ hidden,
                            const float* __restrict__ Wq, const float* __restrict__ Wk,
                            const float* __restrict__ Wv, const float* __restrict__ Wo,
                            fp16* __restrict__ hh, fp16* __restrict__ hl,
                            fp16* __restrict__ qh, fp16* __restrict__ ql,
                            fp16* __restrict__ kh, fp16* __restrict__ kl,
                            fp16* __restrict__ vt, fp16* __restrict__ ot)
{
    const int z = blockIdx.z;
    const int tid = threadIdx.y * 32 + threadIdx.x;
    if (z == 4) {
        int base = (blockIdx.y * (int)gridDim.x + blockIdx.x) * 1024 + tid * 4;
#pragma unroll
        for (int u = 0; u < 4; u++) {
            int i = base + u;
            float4 v = ((const float4*)hidden)[i];
            float vv[4] = {v.x, v.y, v.z, v.w};
            fp16 hhv[4], llv[4];
#pragma unroll
            for (int j = 0; j < 4; j++) spl(vv[j], hhv[j], llv[j]);
            *(ull*)&hh[(size_t)i * 4] = *(ull*)hhv;
            *(ull*)&hl[(size_t)i * 4] = *(ull*)llv;
        }
        return;
    }
    const int N = (z < 2) ? 256 : 1024;
    if (blockIdx.x * 32 >= N) return;
    const float* W = (z == 0) ? Wq : (z == 1) ? Wk : (z == 2) ? Wv : Wo;

    __shared__ float t[32][33];
    int n0 = blockIdx.x * 32, k0 = blockIdx.y * 32;
    int tx = threadIdx.x, ty = threadIdx.y;
#pragma unroll
    for (int i = 0; i < 4; i++)
        t[ty + i * 8][tx] = W[(size_t)(k0 + ty + i * 8) * N + n0 + tx];
    __syncthreads();
    if (z < 2) {
        fp16* thi = (z == 0) ? qh : kh;
        fp16* tlo = (z == 0) ? ql : kl;
#pragma unroll
        for (int i = 0; i < 4; i++) {
            int r = ty + i * 8;
            fp16 h, l;
            spl(t[tx][r], h, l);
            thi[(size_t)(n0 + r) * 1024 + k0 + tx] = h;
            tlo[(size_t)(n0 + r) * 1024 + k0 + tx] = l;
        }
    } else {
        fp16* ts = (z == 2) ? vt : ot;
#pragma unroll
        for (int i = 0; i < 4; i++) {
            int r = ty + i * 8;
            ts[(size_t)(n0 + r) * 1024 + k0 + tx] = __float2half_rn(t[tx][r]);
        }
    }
}

// ---------------------------------------------------------------------------
// GEMM cores: 128x128 tile, 256 threads (2m x 4n), BK=32, 1 sync/stage, occ 2.
// ---------------------------------------------------------------------------
#define ROWB 80
#define MATB (128 * ROWB)
#define STAGEB3 (4 * MATB)
#define GEMM3_SMEM (2 * STAGEB3)
#define STAGEB1 (2 * MATB)
#define GEMM1_SMEM (2 * STAGEB1)

// ---- 3-term (A hi/lo x B hi/lo, drop Al*Bl) ----
#define LOAD_STAGE3(s, buf)                                                             \
    do {                                                                                \
        const int k0 = (s) * 32;                                                        \
        const uint32_t sb_ = sbase + (buf) * STAGEB3;                                   \
        _Pragma("unroll")                                                               \
        for (int t = 0; t < 8; t++) {                                                   \
            int mat = t >> 1;                                                           \
            int sub = (t & 1) * 256 + tid;                                              \
            int row = sub >> 2;                                                         \
            int kc = sub & 3;                                                           \
            const fp16* src = (mat == 0) ? Ahi : (mat == 1) ? Alo                       \
                             : (mat == 2) ? Bhi : Blo;                                  \
            int grow = ((mat < 2) ? rowBase : colBase) + row;                           \
            cp_async16(sb_ + mat * MATB + row * ROWB + kc * 16,                         \
                       src + (size_t)grow * 1024 + k0 + kc * 8);                        \
        }                                                                               \
        cp_commit();                                                                    \
    } while (0)

#define GEMM_MAINLOOP3()                                                                \
    LOAD_STAGE3(0, 0);                                                                  \
    for (int s = 0; s < 32; s++) {                                                      \
        cp_wait0();                                                                     \
        __syncthreads();                                                                \
        if (s + 1 < 32) LOAD_STAGE3(s + 1, (s + 1) & 1);                                \
        const uint32_t sb = sbase + (s & 1) * STAGEB3;                                  \
        _Pragma("unroll")                                                               \
        for (int s2 = 0; s2 < 2; s2++) {                                                \
            const uint32_t kbyte = s2 * 32 + lkb;                                       \
            uint32_t Ah[4][4], Al[4][4];                                                \
            _Pragma("unroll")                                                           \
            for (int mf = 0; mf < 4; mf++) {                                            \
                uint32_t ra = sb + (uint32_t)((wm * 64 + mf * 16 + lrow) * ROWB) + kbyte; \
                ldsm_x4(Ah[mf][0], Ah[mf][1], Ah[mf][2], Ah[mf][3], ra);                \
                ldsm_x4(Al[mf][0], Al[mf][1], Al[mf][2], Al[mf][3], ra + MATB);         \
            }                                                                           \
            uint32_t Bh[4][2], Blr[4][2];                                               \
            _Pragma("unroll")                                                           \
            for (int nf2 = 0; nf2 < 2; nf2++) {                                         \
                uint32_t rb = sb + 2 * MATB +                                           \
                              (uint32_t)((wn * 32 + nf2 * 16 + lrow) * ROWB) + kbyte;   \
                uint32_t q0, q1, q2, q3;                                                \
                ldsm_x4(q0, q1, q2, q3, rb);                                            \
                Bh[nf2 * 2 + 0][0] = q0; Bh[nf2 * 2 + 0][1] = q2;                       \
                Bh[nf2 * 2 + 1][0] = q1; Bh[nf2 * 2 + 1][1] = q3;                       \
                ldsm_x4(q0, q1, q2, q3, rb + MATB);                                     \
                Blr[nf2 * 2 + 0][0] = q0; Blr[nf2 * 2 + 0][1] = q2;                     \
                Blr[nf2 * 2 + 1][0] = q1; Blr[nf2 * 2 + 1][1] = q3;                     \
            }                                                                           \
            _Pragma("unroll")                                                           \
            for (int mf = 0; mf < 4; mf++)                                              \
                _Pragma("unroll")                                                       \
                for (int nf = 0; nf < 4; nf++) {                                        \
                    mma16816(acc[mf][nf], Ah[mf][0], Ah[mf][1], Ah[mf][2], Ah[mf][3],   \
                             Bh[nf][0], Bh[nf][1]);                                     \
                    mma16816(acc[mf][nf], Ah[mf][0], Ah[mf][1], Ah[mf][2], Ah[mf][3],   \
                             Blr[nf][0], Blr[nf][1]);                                   \
                    mma16816(acc[mf][nf], Al[mf][0], Al[mf][1], Al[mf][2], Al[mf][3],   \
                             Bh[nf][0], Bh[nf][1]);                                     \
                }                                                                       \
        }                                                                               \
    }

// ---- 1-term (A single x B single) ----
#define LOAD_STAGE1(s, buf)                                                             \
    do {                                                                                \
        const int k0 = (s) * 32;                                                        \
        const uint32_t sb_ = sbase + (buf) * STAGEB1;                                   \
        _Pragma("unroll")                                                               \
        for (int t = 0; t < 4; t++) {                                                   \
            int idx = t * 256 + tid;                                                    \
            int mat = idx >> 9;                                                         \
            int rem = idx & 511;                                                        \
            int row = rem >> 2;                                                         \
            int kc = rem & 3;                                                           \
            const fp16* src = (mat == 0) ? As : Bs;                                     \
            int grow = ((mat == 0) ? rowBase : colBase) + row;                          \
            cp_async16(sb_ + mat * MATB + row * ROWB + kc * 16,                         \
                       src + (size_t)grow * 1024 + k0 + kc * 8);                        \
        }                                                                               \
        cp_commit();                                                                    \
    } while (0)

#define GEMM_MAINLOOP1()                                                                \
    LOAD_STAGE1(0, 0);                                                                  \
    for (int s = 0; s < 32; s++) {                                                      \
        cp_wait0();                                                                     \
        __syncthreads();                                                                \
        if (s + 1 < 32) LOAD_STAGE1(s + 1, (s + 1) & 1);                                \
        const uint32_t sb = sbase + (s & 1) * STAGEB1;                                  \
        _Pragma("unroll")                                                               \
        for (int s2 = 0; s2 < 2; s2++) {                                                \
            const uint32_t kbyte = s2 * 32 + lkb;                                       \
            uint32_t Ah[4][4];                                                          \
            _Pragma("unroll")                                                           \
            for (int mf = 0; mf < 4; mf++) {                                            \
                uint32_t ra = sb + (uint32_t)((wm * 64 + mf * 16 + lrow) * ROWB) + kbyte; \
                ldsm_x4(Ah[mf][0], Ah[mf][1], Ah[mf][2], Ah[mf][3], ra);                \
            }                                                                           \
            uint32_t Bv[4][2];                                                          \
            _Pragma("unroll")                                                           \
            for (int nf2 = 0; nf2 < 2; nf2++) {                                         \
                uint32_t rb = sb + MATB +                                               \
                              (uint32_t)((wn * 32 + nf2 * 16 + lrow) * ROWB) + kbyte;   \
                uint32_t q0, q1, q2, q3;                                                \
                ldsm_x4(q0, q1, q2, q3, rb);                                            \
                Bv[nf2 * 2 + 0][0] = q0; Bv[nf2 * 2 + 0][1] = q2;                       \
                Bv[nf2 * 2 + 1][0] = q1; Bv[nf2 * 2 + 1][1] = q3;                       \
            }                                                                           \
            _Pragma("unroll")                                                           \
            for (int mf = 0; mf < 4; mf++)                                              \
                _Pragma("unroll")                                                       \
                for (int nf = 0; nf < 4; nf++)                                          \
                    mma16816(acc[mf][nf], Ah[mf][0], Ah[mf][1], Ah[mf][2], Ah[mf][3],   \
                             Bv[nf][0], Bv[nf][1]);                                     \
        }                                                                               \
    }

// ---------------------------------------------------------------------------
// Q & K projections (3-term). tiles: [0,64) Q (x0.25), [64,128) K.
// ---------------------------------------------------------------------------
__global__ __launch_bounds__(256, 2)
void gemm_qk(const fp16* __restrict__ Ahi, const fp16* __restrict__ Alo,
             const fp16* __restrict__ qwh, const fp16* __restrict__ qwl,
             const fp16* __restrict__ kwh, const fp16* __restrict__ kwl,
             fp16* __restrict__ qh, fp16* __restrict__ ql,
             fp16* __restrict__ kh, fp16* __restrict__ kl)
{
    int t = blockIdx.x;
    const bool isQ = (t < 64);
    if (!isQ) t -= 64;
    const fp16* Bhi = isQ ? qwh : kwh;
    const fp16* Blo = isQ ? qwl : kwl;
    fp16* Chi = isQ ? qh : kh;
    fp16* Clo = isQ ? ql : kl;
    const float cs = isQ ? 0.25f : 1.f;
    const int N = 256;
    const int bx = t & 1, by = t >> 1;

    extern __shared__ char smem_raw[];
    const uint32_t sbase = smem_u32(smem_raw);

    const int tid = threadIdx.x;
    const int lane = tid & 31;
    const int warp = tid >> 5;
    const int wm = warp >> 2;
    const int wn = warp & 3;
    const int rowBase = by * 128;
    const int colBase = bx * 128;

    float acc[4][4][4];
#pragma unroll
    for (int i = 0; i < 4; i++)
#pragma unroll
        for (int j = 0; j < 4; j++)
#pragma unroll
            for (int e = 0; e < 4; e++) acc[i][j][e] = 0.f;

    const int lrow = lane & 15;
    const int lkb = ((lane >> 4) & 1) * 16;

    GEMM_MAINLOOP3();

    const int r0b = rowBase + wm * 64 + (lane >> 2);
    const int c0b = colBase + wn * 32 + (lane & 3) * 2;
#pragma unroll
    for (int mf = 0; mf < 4; mf++) {
#pragma unroll
        for (int nf = 0; nf < 4; nf++) {
            int r = r0b + mf * 16;
            int c = c0b + nf * 8;
            float a[4];
#pragma unroll
            for (int e = 0; e < 4; e++) a[e] = acc[mf][nf][e] * cs;
            fp16 h[4], l[4];
#pragma unroll
            for (int e = 0; e < 4; e++) spl(a[e], h[e], l[e]);
            ((uint32_t*)Chi)[((size_t)r * N + c) >> 1] = packh2(h[0], h[1]);
            ((uint32_t*)Clo)[((size_t)r * N + c) >> 1] = packh2(l[0], l[1]);
            ((uint32_t*)Chi)[((size_t)(r + 8) * N + c) >> 1] = packh2(h[2], h[3]);
            ((uint32_t*)Clo)[((size_t)(r + 8) * N + c) >> 1] = packh2(l[2], l[3]);
        }
    }
}

// ---------------------------------------------------------------------------
// V projection (1-term): v = h_hi @ Wv (single fp16 out).
// ---------------------------------------------------------------------------
__global__ __launch_bounds__(256, 2)
void gemm_v(const fp16* __restrict__ As, const fp16* __restrict__ Bs, fp16* __restrict__ V)
{
    extern __shared__ char smem_raw[];
    const uint32_t sbase = smem_u32(smem_raw);

    const int tid = threadIdx.x;
    const int lane = tid & 31;
    const int warp = tid >> 5;
    const int wm = warp >> 2;
    const int wn = warp & 3;
    const int rowBase = blockIdx.y * 128;
    const int colBase = blockIdx.x * 128;
    const int N = 1024;

    float acc[4][4][4];
#pragma unroll
    for (int i = 0; i < 4; i++)
#pragma unroll
        for (int j = 0; j < 4; j++)
#pragma unroll
            for (int e = 0; e < 4; e++) acc[i][j][e] = 0.f;

    const int lrow = lane & 15;
    const int lkb = ((lane >> 4) & 1) * 16;

    GEMM_MAINLOOP1();

    const int r0b = rowBase + wm * 64 + (lane >> 2);
    const int c0b = colBase + wn * 32 + (lane & 3) * 2;
#pragma unroll
    for (int mf = 0; mf < 4; mf++) {
#pragma unroll
        for (int nf = 0; nf < 4; nf++) {
            int r = r0b + mf * 16;
            int c = c0b + nf * 8;
            ((uint32_t*)V)[((size_t)r * N + c) >> 1] =
                packh2(__float2half_rn(acc[mf][nf][0]), __float2half_rn(acc[mf][nf][1]));
            ((uint32_t*)V)[((size_t)(r + 8) * N + c) >> 1] =
                packh2(__float2half_rn(acc[mf][nf][2]), __float2half_rn(acc[mf][nf][3]));
        }
    }
}

// ---------------------------------------------------------------------------
// O projection (1-term): out = o @ Wo, fp32 out.
// ---------------------------------------------------------------------------
__global__ __launch_bounds__(256, 2)
void gemm_out(const fp16* __restrict__ As, const fp16* __restrict__ Bs, float* __restrict__ C)
{
    extern __shared__ char smem_raw[];
    const uint32_t sbase = smem_u32(smem_raw);

    const int tid = threadIdx.x;
    const int lane = tid & 31;
    const int warp = tid >> 5;
    const int wm = warp >> 2;
    const int wn = warp & 3;
    const int rowBase = blockIdx.y * 128;
    const int colBase = blockIdx.x * 128;
    const int N = 1024;

    float acc[4][4][4];
#pragma unroll
    for (int i = 0; i < 4; i++)
#pragma unroll
        for (int j = 0; j < 4; j++)
#pragma unroll
            for (int e = 0; e < 4; e++) acc[i][j][e] = 0.f;

    const int lrow = lane & 15;
    const int lkb = ((lane >> 4) & 1) * 16;

    GEMM_MAINLOOP1();

    const int r0b = rowBase + wm * 64 + (lane >> 2);
    const int c0b = colBase + wn * 32 + (lane & 3) * 2;
#pragma unroll
    for (int mf = 0; mf < 4; mf++) {
#pragma unroll
        for (int nf = 0; nf < 4; nf++) {
            int r = r0b + mf * 16;
            int c = c0b + nf * 8;
            *(float2*)&C[(size_t)r * N + c] = make_float2(acc[mf][nf][0], acc[mf][nf][1]);
            *(float2*)&C[(size_t)(r + 8) * N + c] = make_float2(acc[mf][nf][2], acc[mf][nf][3]);
        }
    }
}

// ---------------------------------------------------------------------------
// Attention: paired query tiles; 128-key loads; QK 3-term, SV 1-term.
// buffer: kh +0 (6144), kl +6144 (6144), v +12288 (18432)  => A_BUFSZ 30720
// ---------------------------------------------------------------------------
#define SQH 0
#define SQL 6144
#define S_TILES 12288
#define A_BUFSZ 30720
#define ATT_SMEM (S_TILES + 2 * A_BUFSZ)
#define SZOFF 33792
#define OSM_STRIDE 66

__global__ __launch_bounds__(256, 2)
void attn_mma(const fp16* __restrict__ qhi, const fp16* __restrict__ qlo,
              const fp16* __restrict__ khi, const fp16* __restrict__ klo,
              const fp16* __restrict__ vv, fp16* __restrict__ oo)
{
    extern __shared__ char smem_raw[];
    const uint32_t sbase = smem_u32(smem_raw);

    const int pr = blockIdx.x;
    const int h = blockIdx.y;
    const int b = blockIdx.z;

    const int tid = threadIdx.x;
    const int lane = tid & 31;
    const int warp = tid >> 5;
    const int wm = warp >> 1;
    const int wn = warp & 1;
    const int lrow = lane & 15;
    const int lkb = ((lane >> 4) & 1) * 16;
    const int lm = lane >> 3;
    const int lr = lane & 7;

#define ATT_LOAD128(t, bsel)                                                             \
    do {                                                                                 \
        const int j0_ = (t) * 128;                                                       \
        const uint32_t bb = sbase + S_TILES + (bsel) * A_BUFSZ;                          \
        _Pragma("unroll")                                                                \
        for (int t2 = 0; t2 < 2; t2++) {                                                 \
            int idx = t2 * 256 + tid;                                                    \
            int arr = idx >> 8;                                                          \
            int rem = idx & 255;                                                         \
            int row = rem >> 1;                                                          \
            int ch = rem & 1;                                                            \
            const fp16* src = arr ? klo : khi;                                           \
            cp_async16(bb + arr * 6144 + row * 48 + ch * 16,                             \
                       src + (size_t)(b * Ll + j0_ + row) * 256 + h * 16 + ch * 8);      \
        }                                                                                \
        _Pragma("unroll")                                                                \
        for (int t2 = 0; t2 < 4; t2++) {                                                 \
            int idx = t2 * 256 + tid;                                                    \
            int row = idx >> 3;                                                          \
            int ch = idx & 7;                                                            \
            cp_async16(bb + 12288 + row * 144 + ch * 16,                                 \
                       vv + (size_t)(b * Ll + j0_ + row) * 1024 + h * 64 + ch * 8);      \
        }                                                                                \
        cp_commit();                                                                     \
    } while (0)

    for (int half = 0; half < 2; half++) {
        const int qt = (half == 0) ? (15 - pr) : pr;
        const int qi0 = qt * 128;
        const int nt = qt + 1;

#pragma unroll
        for (int t = 0; t < 2; t++) {
            int idx = t * 256 + tid;
            int arr = idx >> 8;
            int rem = idx & 255;
            int row = rem >> 1;
            int ch = rem & 1;
            const fp16* src = arr ? qlo : qhi;
            uint4 v = *(const uint4*)&src[(size_t)(b * Ll + qi0 + row) * 256 + h * 16 + ch * 8];
            *(uint4*)(smem_raw + (arr ? SQL : SQH) + row * 48 + ch * 16) = v;
        }
        ATT_LOAD128(0, 0);
        __syncthreads();

        uint32_t Aqh[2][4], Aql[2][4];
#pragma unroll
        for (int mf = 0; mf < 2; mf++) {
            uint32_t ra = sbase + SQH + (uint32_t)((wm * 32 + mf * 16 + lrow) * 48) + lkb;
            ldsm_x4(Aqh[mf][0], Aqh[mf][1], Aqh[mf][2], Aqh[mf][3], ra);
            ldsm_x4(Aql[mf][0], Aql[mf][1], Aql[mf][2], Aql[mf][3], ra + (SQL - SQH));
        }

        float oacc[2][8][4];
#pragma unroll
        for (int i = 0; i < 2; i++)
#pragma unroll
            for (int j = 0; j < 8; j++)
#pragma unroll
                for (int e = 0; e < 4; e++) oacc[i][j][e] = 0.f;
        float zv[2][2] = {{0.f, 0.f}, {0.f, 0.f}};

        for (int t = 0; t < nt; t++) {
            cp_wait0();
            __syncthreads();
            if (t + 1 < nt) ATT_LOAD128(t + 1, (t + 1) & 1);

            const uint32_t bb = sbase + S_TILES + (t & 1) * A_BUFSZ;

#pragma unroll
            for (int sub = 0; sub < 2; sub++) {
                const int j0 = t * 128 + sub * 64;
                const uint32_t kb = bb + (uint32_t)sub * 3072;
                const uint32_t vb = bb + 12288 + (uint32_t)sub * 9216;

                // ---- QK^T (3-term) ----
                float sacc[2][4][4];
#pragma unroll
                for (int i = 0; i < 2; i++)
#pragma unroll
                    for (int j = 0; j < 4; j++)
#pragma unroll
                        for (int e = 0; e < 4; e++) sacc[i][j][e] = 0.f;

#pragma unroll
                for (int nf2 = 0; nf2 < 2; nf2++) {
                    uint32_t ra = kb + (uint32_t)((wn * 32 + nf2 * 16 + lrow) * 48) + lkb;
                    uint32_t kh0, kh1, kh2, kh3, kl0, kl1, kl2, kl3;
                    ldsm_x4(kh0, kh1, kh2, kh3, ra);
                    ldsm_x4(kl0, kl1, kl2, kl3, ra + 6144);
#pragma unroll
                    for (int mf = 0; mf < 2; mf++) {
                        mma16816(sacc[mf][nf2 * 2 + 0], Aqh[mf][0], Aqh[mf][1], Aqh[mf][2], Aqh[mf][3], kh0, kh2);
                        mma16816(sacc[mf][nf2 * 2 + 1], Aqh[mf][0], Aqh[mf][1], Aqh[mf][2], Aqh[mf][3], kh1, kh3);
                    }
#pragma unroll
                    for (int mf = 0; mf < 2; mf++) {
                        mma16816(sacc[mf][nf2 * 2 + 0], Aqh[mf][0], Aqh[mf][1], Aqh[mf][2], Aqh[mf][3], kl0, kl2);
                        mma16816(sacc[mf][nf2 * 2 + 1], Aqh[mf][0], Aqh[mf][1], Aqh[mf][2], Aqh[mf][3], kl1, kl3);
                    }
#pragma unroll
                    for (int mf = 0; mf < 2; mf++) {
                        mma16816(sacc[mf][nf2 * 2 + 0], Aql[mf][0], Aql[mf][1], Aql[mf][2], Aql[mf][3], kh0, kh2);
                        mma16816(sacc[mf][nf2 * 2 + 1], Aql[mf][0], Aql[mf][1], Aql[mf][2], Aql[mf][3], kh1, kh3);
                    }
                }

                // ---- mask ----
                if (j0 + 64 > qi0) {
                    const int rq = qi0 + wm * 32 + (lane >> 2);
                    const int cb0 = j0 + wn * 32 + (lane & 3) * 2;
#pragma unroll
                    for (int mf = 0; mf < 2; mf++) {
                        const int r0 = rq + mf * 16;
                        const int r1 = r0 + 8;
#pragma unroll
                        for (int nf = 0; nf < 4; nf++) {
                            float* c = sacc[mf][nf];
                            const int cb = cb0 + nf * 8;
                            if (cb > r0) c[0] = 0.f;
                            if (cb + 1 > r0) c[1] = 0.f;
                            if (cb > r1) c[2] = 0.f;
                            if (cb + 1 > r1) c[3] = 0.f;
                        }
                    }
                }

                // ---- square, z (exact fp32), repack s -> single fp16 ----
                uint32_t Ash[2][2][4];
#pragma unroll
                for (int mf = 0; mf < 2; mf++) {
#pragma unroll
                    for (int nf = 0; nf < 4; nf++) {
                        float* c = sacc[mf][nf];
                        float s0 = c[0] * c[0];
                        float s1 = c[1] * c[1];
                        float s2 = c[2] * c[2];
                        float s3 = c[3] * c[3];
                        zv[mf][0] += s0 + s1;
                        zv[mf][1] += s2 + s3;
                        int kc = nf >> 1, nfs = nf & 1;
                        Ash[mf][kc][nfs * 2 + 0] = packh2(__float2half_rn(s0), __float2half_rn(s1));
                        Ash[mf][kc][nfs * 2 + 1] = packh2(__float2half_rn(s2), __float2half_rn(s3));
                    }
                }

                // ---- SV (1-term) ----
#pragma unroll
                for (int kc = 0; kc < 2; kc++) {
#pragma unroll
                    for (int nf2 = 0; nf2 < 4; nf2++) {
                        uint32_t av = vb +
                                      (uint32_t)((wn * 32 + kc * 16 + (lm & 1) * 8 + lr) * 144) +
                                      (uint32_t)(nf2 * 32 + (lm >> 1) * 16);
                        uint32_t vh0, vh1, vh2, vh3;
                        ldsm_x4_t(vh0, vh1, vh2, vh3, av);
#pragma unroll
                        for (int mf = 0; mf < 2; mf++) {
                            mma16816(oacc[mf][nf2 * 2 + 0], Ash[mf][kc][0], Ash[mf][kc][1], Ash[mf][kc][2], Ash[mf][kc][3], vh0, vh1);
                            mma16816(oacc[mf][nf2 * 2 + 1], Ash[mf][kc][0], Ash[mf][kc][1], Ash[mf][kc][2], Ash[mf][kc][3], vh2, vh3);
                        }
                    }
                }
            }
        }
        __syncthreads();

        // ---- epilogue ----
#pragma unroll
        for (int mf = 0; mf < 2; mf++)
#pragma unroll
            for (int hf = 0; hf < 2; hf++) {
                zv[mf][hf] += __shfl_xor_sync(0xffffffffu, zv[mf][hf], 1);
                zv[mf][hf] += __shfl_xor_sync(0xffffffffu, zv[mf][hf], 2);
            }

        float* osm = (float*)smem_raw;
        float* zsm = (float*)(smem_raw + SZOFF);

        if (wn == 0) {
#pragma unroll
            for (int mf = 0; mf < 2; mf++) {
                int r0 = wm * 32 + mf * 16 + (lane >> 2);
#pragma unroll
                for (int nf = 0; nf < 8; nf++) {
                    int col = nf * 8 + (lane & 3) * 2;
                    *(float2*)&osm[r0 * OSM_STRIDE + col] = make_float2(oacc[mf][nf][0], oacc[mf][nf][1]);
                    *(float2*)&osm[(r0 + 8) * OSM_STRIDE + col] = make_float2(oacc[mf][nf][2], oacc[mf][nf][3]);
                }
                if ((lane & 3) == 0) {
                    zsm[r0] = zv[mf][0];
                    zsm[r0 + 8] = zv[mf][1];
                }
            }
        }
        __syncthreads();
        if (wn == 1) {
#pragma unroll
            for (int mf = 0; mf < 2; mf++) {
                int r0 = wm * 32 + mf * 16 + (lane >> 2);
                float inv0 = 1.f / (zv[mf][0] + zsm[r0] + 1e-5f);
                float inv1 = 1.f / (zv[mf][1] + zsm[r0 + 8] + 1e-5f);
                size_t g0 = (size_t)(b * Ll + qi0 + r0) * 1024 + h * 64;
                size_t g1 = (size_t)(b * Ll + qi0 + r0 + 8) * 1024 + h * 64;
#pragma unroll
                for (int nf = 0; nf < 8; nf++) {
                    int col = nf * 8 + (lane & 3) * 2;
                    float f0 = (oacc[mf][nf][0] + osm[r0 * OSM_STRIDE + col]) * inv0;
                    float f1 = (oacc[mf][nf][1] + osm[r0 * OSM_STRIDE + col + 1]) * inv0;
                    float f2 = (oacc[mf][nf][2] + osm[(r0 + 8) * OSM_STRIDE + col]) * inv1;
                    float f3 = (oacc[mf][nf][3] + osm[(r0 + 8) * OSM_STRIDE + col + 1]) * inv1;
                    ((uint32_t*)oo)[(g0 + col) >> 1] = packh2(__float2half_rn(f0), __float2half_rn(f1));
                    ((uint32_t*)oo)[(g1 + col) >> 1] = packh2(__float2half_rn(f2), __float2half_rn(f3));
                }
            }
        }
        __syncthreads();
    }
}

// ---------------------------------------------------------------------------
extern "C" void kernel_launch(void* const* d_in, const int* in_sizes, int n_in,
                              void* d_out, int out_size)
{
    const float* hidden = (const float*)d_in[0];
    const float* Wq = (const float*)d_in[1];
    const float* Wk = (const float*)d_in[2];
    const float* Wv = (const float*)d_in[3];
    const float* Wo = (const float*)d_in[4];
    float* out = (float*)d_out;

    fp16 *hhi, *hlo, *qhi, *qlo, *khi, *klo, *vv, *oo;
    cudaGetSymbolAddress((void**)&hhi, g_hhi);
    cudaGetSymbolAddress((void**)&hlo, g_hlo);
    cudaGetSymbolAddress((void**)&qhi, g_qhi);
    cudaGetSymbolAddress((void**)&qlo, g_qlo);
    cudaGetSymbolAddress((void**)&khi, g_khi);
    cudaGetSymbolAddress((void**)&klo, g_klo);
    cudaGetSymbolAddress((void**)&vv, g_v);
    cudaGetSymbolAddress((void**)&oo, g_o);
    fp16 *wqh, *wql, *wkh, *wkl, *wvt, *wot;
    cudaGetSymbolAddress((void**)&wqh, g_wqt_hi);
    cudaGetSymbolAddress((void**)&wql, g_wqt_lo);
    cudaGetSymbolAddress((void**)&wkh, g_wkt_hi);
    cudaGetSymbolAddress((void**)&wkl, g_wkt_lo);
    cudaGetSymbolAddress((void**)&wvt, g_wvt);
    cudaGetSymbolAddress((void**)&wot, g_wot);

    cudaFuncSetAttribute(gemm_qk, cudaFuncAttributeMaxDynamicSharedMemorySize, GEMM3_SMEM);
    cudaFuncSetAttribute(gemm_v, cudaFuncAttributeMaxDynamicSharedMemorySize, GEMM1_SMEM);
    cudaFuncSetAttribute(gemm_out, cudaFuncAttributeMaxDynamicSharedMemorySize, GEMM1_SMEM);
    cudaFuncSetAttribute(attn_mma, cudaFuncAttributeMaxDynamicSharedMemorySize, ATT_SMEM);

    convert_all<<<dim3(32, 32, 5), dim3(32, 8)>>>(hidden, Wq, Wk, Wv, Wo,
        hhi, hlo, wqh, wql, wkh, wkl, wvt, wot);

    gemm_qk<<<128, 256, GEMM3_SMEM>>>(hhi, hlo, wqh, wql, wkh, wkl, qhi, qlo, khi, klo);
    gemm_v<<<dim3(8, 32), 256, GEMM1_SMEM>>>(hhi, wvt, vv);
    attn_mma<<<dim3(8, Hh, Bb), 256, ATT_SMEM>>>(qhi, qlo, khi, klo, vv, oo);
    gemm_out<<<dim3(8, 32), 256, GEMM1_SMEM>>>(oo, wot, out);
}

// round 15
// speedup vs baseline: 1.8678x; 1.0488x over previous
#include <cuda_runtime.h>
#include <cuda_fp16.h>
#include <stdint.h>

// ReBasedLinearAttention: B=2, L=2048, D=1024, H=16, FD=16, HD=64
// fp16 mma.sync at HMMA issue floor. Precision plan:
//   Q/K proj: 3-term compute; q stored hi/lo, k stored SINGLE
//   QK^T    : 2-term (qh x ks + ql x ks)
//   V proj, SV, Out: 1-term; z exact fp32

#define Bb 2
#define Ll 2048
#define Dd 1024
#define Hh 16
#define BL (Bb * Ll)

typedef unsigned long long ull;
typedef __half fp16;

// ---------------- scratch ----------------
__device__ fp16 g_hhi[BL * 1024];
__device__ fp16 g_hlo[BL * 1024];
__device__ fp16 g_qhi[BL * 256];
__device__ fp16 g_qlo[BL * 256];
__device__ fp16 g_k[BL * 256];
__device__ fp16 g_v[BL * 1024];
__device__ fp16 g_o[BL * 1024];

__device__ fp16 g_wqt_hi[256 * 1024];
__device__ fp16 g_wqt_lo[256 * 1024];
__device__ fp16 g_wkt_hi[256 * 1024];
__device__ fp16 g_wkt_lo[256 * 1024];
__device__ fp16 g_wvt[1024 * 1024];
__device__ fp16 g_wot[1024 * 1024];

// ---------------- PTX helpers ----------------
__device__ __forceinline__ uint32_t smem_u32(const void* p) {
    uint32_t a;
    asm("{ .reg .u64 t; cvta.to.shared.u64 t, %1; cvt.u32.u64 %0, t; }" : "=r"(a) : "l"(p));
    return a;
}
__device__ __forceinline__ void cp_async16(uint32_t saddr, const void* gaddr) {
    asm volatile("cp.async.cg.shared.global [%0], [%1], 16;" :: "r"(saddr), "l"(gaddr) : "memory");
}
__device__ __forceinline__ void cp_commit() {
    asm volatile("cp.async.commit_group;" ::: "memory");
}
__device__ __forceinline__ void cp_wait0() {
    asm volatile("cp.async.wait_group 0;" ::: "memory");
}
__device__ __forceinline__ void ldsm_x4(uint32_t& r0, uint32_t& r1, uint32_t& r2, uint32_t& r3,
                                        uint32_t addr) {
    asm volatile("ldmatrix.sync.aligned.m8n8.x4.shared.b16 {%0,%1,%2,%3}, [%4];"
                 : "=r"(r0), "=r"(r1), "=r"(r2), "=r"(r3) : "r"(addr));
}
__device__ __forceinline__ void ldsm_x4_t(uint32_t& r0, uint32_t& r1, uint32_t& r2, uint32_t& r3,
                                          uint32_t addr) {
    asm volatile("ldmatrix.sync.aligned.m8n8.x4.trans.shared.b16 {%0,%1,%2,%3}, [%4];"
                 : "=r"(r0), "=r"(r1), "=r"(r2), "=r"(r3) : "r"(addr));
}
__device__ __forceinline__ void mma16816(float c[4], uint32_t a0, uint32_t a1, uint32_t a2,
                                         uint32_t a3, uint32_t b0, uint32_t b1) {
    asm volatile(
        "mma.sync.aligned.m16n8k16.row.col.f32.f16.f16.f32 "
        "{%0,%1,%2,%3}, {%4,%5,%6,%7}, {%8,%9}, {%0,%1,%2,%3};"
        : "+f"(c[0]), "+f"(c[1]), "+f"(c[2]), "+f"(c[3])
        : "r"(a0), "r"(a1), "r"(a2), "r"(a3), "r"(b0), "r"(b1));
}
__device__ __forceinline__ uint32_t packh2(fp16 lo, fp16 hi) {
    __half2 t = __halves2half2(lo, hi);
    return *reinterpret_cast<uint32_t*>(&t);
}
__device__ __forceinline__ void spl(float x, fp16& h, fp16& l) {
    h = __float2half_rn(x);
    l = __float2half_rn(x - __half2float(h));
}

// ---------------------------------------------------------------------------
// Conversions: z 0=Wq(hi/lo) 1=Wk(hi/lo) 2=Wv(single) 3=Wo(single) 4=hidden split
// ---------------------------------------------------------------------------
__global__ void convert_all(const float* __restrict__ hidden,
                            const float* __restrict__ Wq, const float* __restrict__ Wk,
                            const float* __restrict__ Wv, const float* __restrict__ Wo,
                            fp16* __restrict__ hh, fp16* __restrict__ hl,
                            fp16* __restrict__ qh, fp16* __restrict__ ql,
                            fp16* __restrict__ kh, fp16* __restrict__ kl,
                            fp16* __restrict__ vt, fp16* __restrict__ ot)
{
    const int z = blockIdx.z;
    const int tid = threadIdx.y * 32 + threadIdx.x;
    if (z == 4) {
        int base = (blockIdx.y * (int)gridDim.x + blockIdx.x) * 1024 + tid * 4;
#pragma unroll
        for (int u = 0; u < 4; u++) {
            int i = base + u;
            float4 v = ((const float4*)hidden)[i];
            float vv[4] = {v.x, v.y, v.z, v.w};
            fp16 hhv[4], llv[4];
#pragma unroll
            for (int j = 0; j < 4; j++) spl(vv[j], hhv[j], llv[j]);
            *(ull*)&hh[(size_t)i * 4] = *(ull*)hhv;
            *(ull*)&hl[(size_t)i * 4] = *(ull*)llv;
        }
        return;
    }
    const int N = (z < 2) ? 256 : 1024;
    if (blockIdx.x * 32 >= N) return;
    const float* W = (z == 0) ? Wq : (z == 1) ? Wk : (z == 2) ? Wv : Wo;

    __shared__ float t[32][33];
    int n0 = blockIdx.x * 32, k0 = blockIdx.y * 32;
    int tx = threadIdx.x, ty = threadIdx.y;
#pragma unroll
    for (int i = 0; i < 4; i++)
        t[ty + i * 8][tx] = W[(size_t)(k0 + ty + i * 8) * N + n0 + tx];
    __syncthreads();
    if (z < 2) {
        fp16* thi = (z == 0) ? qh : kh;
        fp16* tlo = (z == 0) ? ql : kl;
#pragma unroll
        for (int i = 0; i < 4; i++) {
            int r = ty + i * 8;
            fp16 h, l;
            spl(t[tx][r], h, l);
            thi[(size_t)(n0 + r) * 1024 + k0 + tx] = h;
            tlo[(size_t)(n0 + r) * 1024 + k0 + tx] = l;
        }
    } else {
        fp16* ts = (z == 2) ? vt : ot;
#pragma unroll
        for (int i = 0; i < 4; i++) {
            int r = ty + i * 8;
            ts[(size_t)(n0 + r) * 1024 + k0 + tx] = __float2half_rn(t[tx][r]);
        }
    }
}

// ---------------------------------------------------------------------------
// Q/K projection: 64x128 CTA tile (256 CTAs), 3-term compute.
// tiles: [0,128) Q (x0.25, hi/lo out), [128,256) K (single out).
// warps: 2m x 4n -> 32x32 warp tile.
// ---------------------------------------------------------------------------
#define ROWB 80
#define QK_A_MATB (64 * ROWB)    // 5120
#define QK_B_MATB (128 * ROWB)   // 10240
#define QK_BOFF (2 * QK_A_MATB)
#define QK_STAGEB (2 * QK_A_MATB + 2 * QK_B_MATB)  // 30720
#define QK_SMEM (2 * QK_STAGEB)                    // 61440

__global__ __launch_bounds__(256, 2)
void gemm_qk(const fp16* __restrict__ Ahi, const fp16* __restrict__ Alo,
             const fp16* __restrict__ qwh, const fp16* __restrict__ qwl,
             const fp16* __restrict__ kwh, const fp16* __restrict__ kwl,
             fp16* __restrict__ qh, fp16* __restrict__ ql, fp16* __restrict__ ks)
{
    int t = blockIdx.x;
    const bool isQ = (t < 128);
    if (!isQ) t -= 128;
    const fp16* Bhi = isQ ? qwh : kwh;
    const fp16* Blo = isQ ? qwl : kwl;
    const int N = 256;
    const int bx = t & 1, by = t >> 1;       // by 0..63
    const int rowBase = by * 64;
    const int colBase = bx * 128;

    extern __shared__ char smem_raw[];
    const uint32_t sbase = smem_u32(smem_raw);

    const int tid = threadIdx.x;
    const int lane = tid & 31;
    const int warp = tid >> 5;
    const int wm = warp >> 2;   // 0..1
    const int wn = warp & 3;    // 0..3
    const int lrow = lane & 15;
    const int lkb = ((lane >> 4) & 1) * 16;

    float acc[2][4][4];
#pragma unroll
    for (int i = 0; i < 2; i++)
#pragma unroll
        for (int j = 0; j < 4; j++)
#pragma unroll
            for (int e = 0; e < 4; e++) acc[i][j][e] = 0.f;

#define QK_LOAD(s, buf)                                                                 \
    do {                                                                                \
        const int k0 = (s) * 32;                                                        \
        const uint32_t sb_ = sbase + (buf) * QK_STAGEB;                                 \
        _Pragma("unroll")                                                               \
        for (int tt = 0; tt < 6; tt++) {                                                \
            int idx = tt * 256 + tid;                                                   \
            if (idx < 512) {                                                            \
                int mat = idx >> 8;                                                     \
                int rem = idx & 255;                                                    \
                int row = rem >> 2;                                                     \
                int kc = rem & 3;                                                       \
                const fp16* src = mat ? Alo : Ahi;                                      \
                cp_async16(sb_ + mat * QK_A_MATB + row * ROWB + kc * 16,                \
                           src + (size_t)(rowBase + row) * 1024 + k0 + kc * 8);         \
            } else {                                                                    \
                int idx2 = idx - 512;                                                   \
                int mat = idx2 >> 9;                                                    \
                int rem = idx2 & 511;                                                   \
                int row = rem >> 2;                                                     \
                int kc = rem & 3;                                                       \
                const fp16* src = mat ? Blo : Bhi;                                      \
                cp_async16(sb_ + QK_BOFF + mat * QK_B_MATB + row * ROWB + kc * 16,      \
                           src + (size_t)(colBase + row) * 1024 + k0 + kc * 8);         \
            }                                                                           \
        }                                                                               \
        cp_commit();                                                                    \
    } while (0)

    QK_LOAD(0, 0);
    for (int s = 0; s < 32; s++) {
        cp_wait0();
        __syncthreads();
        if (s + 1 < 32) QK_LOAD(s + 1, (s + 1) & 1);
        const uint32_t sb = sbase + (s & 1) * QK_STAGEB;
#pragma unroll
        for (int s2 = 0; s2 < 2; s2++) {
            const uint32_t kbyte = s2 * 32 + lkb;
            uint32_t Ah[2][4], Al[2][4];
#pragma unroll
            for (int mf = 0; mf < 2; mf++) {
                uint32_t ra = sb + (uint32_t)((wm * 32 + mf * 16 + lrow) * ROWB) + kbyte;
                ldsm_x4(Ah[mf][0], Ah[mf][1], Ah[mf][2], Ah[mf][3], ra);
                ldsm_x4(Al[mf][0], Al[mf][1], Al[mf][2], Al[mf][3], ra + QK_A_MATB);
            }
            uint32_t Bh[4][2], Blr[4][2];
#pragma unroll
            for (int nf2 = 0; nf2 < 2; nf2++) {
                uint32_t rb = sb + QK_BOFF +
                              (uint32_t)((wn * 32 + nf2 * 16 + lrow) * ROWB) + kbyte;
                uint32_t q0, q1, q2, q3;
                ldsm_x4(q0, q1, q2, q3, rb);
                Bh[nf2 * 2 + 0][0] = q0; Bh[nf2 * 2 + 0][1] = q2;
                Bh[nf2 * 2 + 1][0] = q1; Bh[nf2 * 2 + 1][1] = q3;
                ldsm_x4(q0, q1, q2, q3, rb + QK_B_MATB);
                Blr[nf2 * 2 + 0][0] = q0; Blr[nf2 * 2 + 0][1] = q2;
                Blr[nf2 * 2 + 1][0] = q1; Blr[nf2 * 2 + 1][1] = q3;
            }
#pragma unroll
            for (int mf = 0; mf < 2; mf++)
#pragma unroll
                for (int nf = 0; nf < 4; nf++) {
                    mma16816(acc[mf][nf], Ah[mf][0], Ah[mf][1], Ah[mf][2], Ah[mf][3],
                             Bh[nf][0], Bh[nf][1]);
                    mma16816(acc[mf][nf], Ah[mf][0], Ah[mf][1], Ah[mf][2], Ah[mf][3],
                             Blr[nf][0], Blr[nf][1]);
                    mma16816(acc[mf][nf], Al[mf][0], Al[mf][1], Al[mf][2], Al[mf][3],
                             Bh[nf][0], Bh[nf][1]);
                }
        }
    }

    const int r0b = rowBase + wm * 32 + (lane >> 2);
    const int c0b = colBase + wn * 32 + (lane & 3) * 2;
#pragma unroll
    for (int mf = 0; mf < 2; mf++) {
#pragma unroll
        for (int nf = 0; nf < 4; nf++) {
            int r = r0b + mf * 16;
            int c = c0b + nf * 8;
            if (isQ) {
                float a[4];
#pragma unroll
                for (int e = 0; e < 4; e++) a[e] = acc[mf][nf][e] * 0.25f;
                fp16 h[4], l[4];
#pragma unroll
                for (int e = 0; e < 4; e++) spl(a[e], h[e], l[e]);
                ((uint32_t*)qh)[((size_t)r * N + c) >> 1] = packh2(h[0], h[1]);
                ((uint32_t*)ql)[((size_t)r * N + c) >> 1] = packh2(l[0], l[1]);
                ((uint32_t*)qh)[((size_t)(r + 8) * N + c) >> 1] = packh2(h[2], h[3]);
                ((uint32_t*)ql)[((size_t)(r + 8) * N + c) >> 1] = packh2(l[2], l[3]);
            } else {
                ((uint32_t*)ks)[((size_t)r * N + c) >> 1] =
                    packh2(__float2half_rn(acc[mf][nf][0]), __float2half_rn(acc[mf][nf][1]));
                ((uint32_t*)ks)[((size_t)(r + 8) * N + c) >> 1] =
                    packh2(__float2half_rn(acc[mf][nf][2]), __float2half_rn(acc[mf][nf][3]));
            }
        }
    }
}

// ---------------------------------------------------------------------------
// 1-term GEMM core (128x128 tile, 256 threads, 2m x 4n).
// ---------------------------------------------------------------------------
#define MATB (128 * ROWB)
#define STAGEB1 (2 * MATB)
#define GEMM1_SMEM (2 * STAGEB1)

#define LOAD_STAGE1(s, buf)                                                             \
    do {                                                                                \
        const int k0 = (s) * 32;                                                        \
        const uint32_t sb_ = sbase + (buf) * STAGEB1;                                   \
        _Pragma("unroll")                                                               \
        for (int tt = 0; tt < 4; tt++) {                                                \
            int idx = tt * 256 + tid;                                                   \
            int mat = idx >> 9;                                                         \
            int rem = idx & 511;                                                        \
            int row = rem >> 2;                                                         \
            int kc = rem & 3;                                                           \
            const fp16* src = (mat == 0) ? As : Bs;                                     \
            int grow = ((mat == 0) ? rowBase : colBase) + row;                          \
            cp_async16(sb_ + mat * MATB + row * ROWB + kc * 16,                         \
                       src + (size_t)grow * 1024 + k0 + kc * 8);                        \
        }                                                                               \
        cp_commit();                                                                    \
    } while (0)

#define GEMM_MAINLOOP1()                                                                \
    LOAD_STAGE1(0, 0);                                                                  \
    for (int s = 0; s < 32; s++) {                                                      \
        cp_wait0();                                                                     \
        __syncthreads();                                                                \
        if (s + 1 < 32) LOAD_STAGE1(s + 1, (s + 1) & 1);                                \
        const uint32_t sb = sbase + (s & 1) * STAGEB1;                                  \
        _Pragma("unroll")                                                               \
        for (int s2 = 0; s2 < 2; s2++) {                                                \
            const uint32_t kbyte = s2 * 32 + lkb;                                       \
            uint32_t Ah[4][4];                                                          \
            _Pragma("unroll")                                                           \
            for (int mf = 0; mf < 4; mf++) {                                            \
                uint32_t ra = sb + (uint32_t)((wm * 64 + mf * 16 + lrow) * ROWB) + kbyte; \
                ldsm_x4(Ah[mf][0], Ah[mf][1], Ah[mf][2], Ah[mf][3], ra);                \
            }                                                                           \
            uint32_t Bv[4][2];                                                          \
            _Pragma("unroll")                                                           \
            for (int nf2 = 0; nf2 < 2; nf2++) {                                         \
                uint32_t rb = sb + MATB +                                               \
                              (uint32_t)((wn * 32 + nf2 * 16 + lrow) * ROWB) + kbyte;   \
                uint32_t q0, q1, q2, q3;                                                \
                ldsm_x4(q0, q1, q2, q3, rb);                                            \
                Bv[nf2 * 2 + 0][0] = q0; Bv[nf2 * 2 + 0][1] = q2;                       \
                Bv[nf2 * 2 + 1][0] = q1; Bv[nf2 * 2 + 1][1] = q3;                       \
            }                                                                           \
            _Pragma("unroll")                                                           \
            for (int mf = 0; mf < 4; mf++)                                              \
                _Pragma("unroll")                                                       \
                for (int nf = 0; nf < 4; nf++)                                          \
                    mma16816(acc[mf][nf], Ah[mf][0], Ah[mf][1], Ah[mf][2], Ah[mf][3],   \
                             Bv[nf][0], Bv[nf][1]);                                     \
        }                                                                               \
    }

__global__ __launch_bounds__(256, 2)
void gemm_v(const fp16* __restrict__ As, const fp16* __restrict__ Bs, fp16* __restrict__ V)
{
    extern __shared__ char smem_raw[];
    const uint32_t sbase = smem_u32(smem_raw);
    const int tid = threadIdx.x;
    const int lane = tid & 31;
    const int warp = tid >> 5;
    const int wm = warp >> 2;
    const int wn = warp & 3;
    const int rowBase = blockIdx.y * 128;
    const int colBase = blockIdx.x * 128;
    const int N = 1024;

    float acc[4][4][4];
#pragma unroll
    for (int i = 0; i < 4; i++)
#pragma unroll
        for (int j = 0; j < 4; j++)
#pragma unroll
            for (int e = 0; e < 4; e++) acc[i][j][e] = 0.f;

    const int lrow = lane & 15;
    const int lkb = ((lane >> 4) & 1) * 16;

    GEMM_MAINLOOP1();

    const int r0b = rowBase + wm * 64 + (lane >> 2);
    const int c0b = colBase + wn * 32 + (lane & 3) * 2;
#pragma unroll
    for (int mf = 0; mf < 4; mf++) {
#pragma unroll
        for (int nf = 0; nf < 4; nf++) {
            int r = r0b + mf * 16;
            int c = c0b + nf * 8;
            ((uint32_t*)V)[((size_t)r * N + c) >> 1] =
                packh2(__float2half_rn(acc[mf][nf][0]), __float2half_rn(acc[mf][nf][1]));
            ((uint32_t*)V)[((size_t)(r + 8) * N + c) >> 1] =
                packh2(__float2half_rn(acc[mf][nf][2]), __float2half_rn(acc[mf][nf][3]));
        }
    }
}

__global__ __launch_bounds__(256, 2)
void gemm_out(const fp16* __restrict__ As, const fp16* __restrict__ Bs, float* __restrict__ C)
{
    extern __shared__ char smem_raw[];
    const uint32_t sbase = smem_u32(smem_raw);
    const int tid = threadIdx.x;
    const int lane = tid & 31;
    const int warp = tid >> 5;
    const int wm = warp >> 2;
    const int wn = warp & 3;
    const int rowBase = blockIdx.y * 128;
    const int colBase = blockIdx.x * 128;
    const int N = 1024;

    float acc[4][4][4];
#pragma unroll
    for (int i = 0; i < 4; i++)
#pragma unroll
        for (int j = 0; j < 4; j++)
#pragma unroll
            for (int e = 0; e < 4; e++) acc[i][j][e] = 0.f;

    const int lrow = lane & 15;
    const int lkb = ((lane >> 4) & 1) * 16;

    GEMM_MAINLOOP1();

    const int r0b = rowBase + wm * 64 + (lane >> 2);
    const int c0b = colBase + wn * 32 + (lane & 3) * 2;
#pragma unroll
    for (int mf = 0; mf < 4; mf++) {
#pragma unroll
        for (int nf = 0; nf < 4; nf++) {
            int r = r0b + mf * 16;
            int c = c0b + nf * 8;
            *(float2*)&C[(size_t)r * N + c] = make_float2(acc[mf][nf][0], acc[mf][nf][1]);
            *(float2*)&C[(size_t)(r + 8) * N + c] = make_float2(acc[mf][nf][2], acc[mf][nf][3]);
        }
    }
}

// ---------------------------------------------------------------------------
// Attention: paired query tiles; 128-key loads; QK 2-term (k single), SV 1-term.
// buffer: ks +0 (6144), v +6144 (18432)  => A_BUFSZ 24576
// ---------------------------------------------------------------------------
#define SQH 0
#define SQL 6144
#define S_TILES 12288
#define A_BUFSZ 24576
#define ATT_SMEM (S_TILES + 2 * A_BUFSZ)  // 61440
#define SZOFF 33792
#define OSM_STRIDE 66

__global__ __launch_bounds__(256, 2)
void attn_mma(const fp16* __restrict__ qhi, const fp16* __restrict__ qlo,
              const fp16* __restrict__ kk, const fp16* __restrict__ vv,
              fp16* __restrict__ oo)
{
    extern __shared__ char smem_raw[];
    const uint32_t sbase = smem_u32(smem_raw);

    const int pr = blockIdx.x;
    const int h = blockIdx.y;
    const int b = blockIdx.z;

    const int tid = threadIdx.x;
    const int lane = tid & 31;
    const int warp = tid >> 5;
    const int wm = warp >> 1;
    const int wn = warp & 1;
    const int lrow = lane & 15;
    const int lkb = ((lane >> 4) & 1) * 16;
    const int lm = lane >> 3;
    const int lr = lane & 7;

#define ATT_LOAD128(t, bsel)                                                             \
    do {                                                                                 \
        const int j0_ = (t) * 128;                                                       \
        const uint32_t bb = sbase + S_TILES + (bsel) * A_BUFSZ;                          \
        {                                                                                \
            int row = tid >> 1;                                                          \
            int ch = tid & 1;                                                            \
            cp_async16(bb + row * 48 + ch * 16,                                          \
                       kk + (size_t)(b * Ll + j0_ + row) * 256 + h * 16 + ch * 8);       \
        }                                                                                \
        _Pragma("unroll")                                                                \
        for (int t2 = 0; t2 < 4; t2++) {                                                 \
            int idx = t2 * 256 + tid;                                                    \
            int row = idx >> 3;                                                          \
            int ch = idx & 7;                                                            \
            cp_async16(bb + 6144 + row * 144 + ch * 16,                                  \
                       vv + (size_t)(b * Ll + j0_ + row) * 1024 + h * 64 + ch * 8);      \
        }                                                                                \
        cp_commit();                                                                     \
    } while (0)

    for (int half = 0; half < 2; half++) {
        const int qt = (half == 0) ? (15 - pr) : pr;
        const int qi0 = qt * 128;
        const int nt = qt + 1;

#pragma unroll
        for (int t = 0; t < 2; t++) {
            int idx = t * 256 + tid;
            int arr = idx >> 8;
            int rem = idx & 255;
            int row = rem >> 1;
            int ch = rem & 1;
            const fp16* src = arr ? qlo : qhi;
            uint4 v = *(const uint4*)&src[(size_t)(b * Ll + qi0 + row) * 256 + h * 16 + ch * 8];
            *(uint4*)(smem_raw + (arr ? SQL : SQH) + row * 48 + ch * 16) = v;
        }
        ATT_LOAD128(0, 0);
        __syncthreads();

        uint32_t Aqh[2][4], Aql[2][4];
#pragma unroll
        for (int mf = 0; mf < 2; mf++) {
            uint32_t ra = sbase + SQH + (uint32_t)((wm * 32 + mf * 16 + lrow) * 48) + lkb;
            ldsm_x4(Aqh[mf][0], Aqh[mf][1], Aqh[mf][2], Aqh[mf][3], ra);
            ldsm_x4(Aql[mf][0], Aql[mf][1], Aql[mf][2], Aql[mf][3], ra + (SQL - SQH));
        }

        float oacc[2][8][4];
#pragma unroll
        for (int i = 0; i < 2; i++)
#pragma unroll
            for (int j = 0; j < 8; j++)
#pragma unroll
                for (int e = 0; e < 4; e++) oacc[i][j][e] = 0.f;
        float zv[2][2] = {{0.f, 0.f}, {0.f, 0.f}};

        for (int t = 0; t < nt; t++) {
            cp_wait0();
            __syncthreads();
            if (t + 1 < nt) ATT_LOAD128(t + 1, (t + 1) & 1);

            const uint32_t bb = sbase + S_TILES + (t & 1) * A_BUFSZ;

#pragma unroll
            for (int sub = 0; sub < 2; sub++) {
                const int j0 = t * 128 + sub * 64;
                const uint32_t kb = bb + (uint32_t)sub * 3072;
                const uint32_t vb = bb + 6144 + (uint32_t)sub * 9216;

                // ---- QK^T (2-term: q hi/lo x k single) ----
                float sacc[2][4][4];
#pragma unroll
                for (int i = 0; i < 2; i++)
#pragma unroll
                    for (int j = 0; j < 4; j++)
#pragma unroll
                        for (int e = 0; e < 4; e++) sacc[i][j][e] = 0.f;

#pragma unroll
                for (int nf2 = 0; nf2 < 2; nf2++) {
                    uint32_t ra = kb + (uint32_t)((wn * 32 + nf2 * 16 + lrow) * 48) + lkb;
                    uint32_t kh0, kh1, kh2, kh3;
                    ldsm_x4(kh0, kh1, kh2, kh3, ra);
#pragma unroll
                    for (int mf = 0; mf < 2; mf++) {
                        mma16816(sacc[mf][nf2 * 2 + 0], Aqh[mf][0], Aqh[mf][1], Aqh[mf][2], Aqh[mf][3], kh0, kh2);
                        mma16816(sacc[mf][nf2 * 2 + 1], Aqh[mf][0], Aqh[mf][1], Aqh[mf][2], Aqh[mf][3], kh1, kh3);
                    }
#pragma unroll
                    for (int mf = 0; mf < 2; mf++) {
                        mma16816(sacc[mf][nf2 * 2 + 0], Aql[mf][0], Aql[mf][1], Aql[mf][2], Aql[mf][3], kh0, kh2);
                        mma16816(sacc[mf][nf2 * 2 + 1], Aql[mf][0], Aql[mf][1], Aql[mf][2], Aql[mf][3], kh1, kh3);
                    }
                }

                // ---- mask ----
                if (j0 + 64 > qi0) {
                    const int rq = qi0 + wm * 32 + (lane >> 2);
                    const int cb0 = j0 + wn * 32 + (lane & 3) * 2;
#pragma unroll
                    for (int mf = 0; mf < 2; mf++) {
                        const int r0 = rq + mf * 16;
                        const int r1 = r0 + 8;
#pragma unroll
                        for (int nf = 0; nf < 4; nf++) {
                            float* c = sacc[mf][nf];
                            const int cb = cb0 + nf * 8;
                            if (cb > r0) c[0] = 0.f;
                            if (cb + 1 > r0) c[1] = 0.f;
                            if (cb > r1) c[2] = 0.f;
                            if (cb + 1 > r1) c[3] = 0.f;
                        }
                    }
                }

                // ---- square, z (fp32), repack s -> single fp16 ----
                uint32_t Ash[2][2][4];
#pragma unroll
                for (int mf = 0; mf < 2; mf++) {
#pragma unroll
                    for (int nf = 0; nf < 4; nf++) {
                        float* c = sacc[mf][nf];
                        float s0 = c[0] * c[0];
                        float s1 = c[1] * c[1];
                        float s2 = c[2] * c[2];
                        float s3 = c[3] * c[3];
                        zv[mf][0] += s0 + s1;
                        zv[mf][1] += s2 + s3;
                        int kc = nf >> 1, nfs = nf & 1;
                        Ash[mf][kc][nfs * 2 + 0] = packh2(__float2half_rn(s0), __float2half_rn(s1));
                        Ash[mf][kc][nfs * 2 + 1] = packh2(__float2half_rn(s2), __float2half_rn(s3));
                    }
                }

                // ---- SV (1-term) ----
#pragma unroll
                for (int kc = 0; kc < 2; kc++) {
#pragma unroll
                    for (int nf2 = 0; nf2 < 4; nf2++) {
                        uint32_t av = vb +
                                      (uint32_t)((wn * 32 + kc * 16 + (lm & 1) * 8 + lr) * 144) +
                                      (uint32_t)(nf2 * 32 + (lm >> 1) * 16);
                        uint32_t vh0, vh1, vh2, vh3;
                        ldsm_x4_t(vh0, vh1, vh2, vh3, av);
#pragma unroll
                        for (int mf = 0; mf < 2; mf++) {
                            mma16816(oacc[mf][nf2 * 2 + 0], Ash[mf][kc][0], Ash[mf][kc][1], Ash[mf][kc][2], Ash[mf][kc][3], vh0, vh1);
                            mma16816(oacc[mf][nf2 * 2 + 1], Ash[mf][kc][0], Ash[mf][kc][1], Ash[mf][kc][2], Ash[mf][kc][3], vh2, vh3);
                        }
                    }
                }
            }
        }
        __syncthreads();

        // ---- epilogue ----
#pragma unroll
        for (int mf = 0; mf < 2; mf++)
#pragma unroll
            for (int hf = 0; hf < 2; hf++) {
                zv[mf][hf] += __shfl_xor_sync(0xffffffffu, zv[mf][hf], 1);
                zv[mf][hf] += __shfl_xor_sync(0xffffffffu, zv[mf][hf], 2);
            }

        float* osm = (float*)smem_raw;
        float* zsm = (float*)(smem_raw + SZOFF);

        if (wn == 0) {
#pragma unroll
            for (int mf = 0; mf < 2; mf++) {
                int r0 = wm * 32 + mf * 16 + (lane >> 2);
#pragma unroll
                for (int nf = 0; nf < 8; nf++) {
                    int col = nf * 8 + (lane & 3) * 2;
                    *(float2*)&osm[r0 * OSM_STRIDE + col] = make_float2(oacc[mf][nf][0], oacc[mf][nf][1]);
                    *(float2*)&osm[(r0 + 8) * OSM_STRIDE + col] = make_float2(oacc[mf][nf][2], oacc[mf][nf][3]);
                }
                if ((lane & 3) == 0) {
                    zsm[r0] = zv[mf][0];
                    zsm[r0 + 8] = zv[mf][1];
                }
            }
        }
        __syncthreads();
        if (wn == 1) {
#pragma unroll
            for (int mf = 0; mf < 2; mf++) {
                int r0 = wm * 32 + mf * 16 + (lane >> 2);
                float inv0 = 1.f / (zv[mf][0] + zsm[r0] + 1e-5f);
                float inv1 = 1.f / (zv[mf][1] + zsm[r0 + 8] + 1e-5f);
                size_t g0 = (size_t)(b * Ll + qi0 + r0) * 1024 + h * 64;
                size_t g1 = (size_t)(b * Ll + qi0 + r0 + 8) * 1024 + h * 64;
#pragma unroll
                for (int nf = 0; nf < 8; nf++) {
                    int col = nf * 8 + (lane & 3) * 2;
                    float f0 = (oacc[mf][nf][0] + osm[r0 * OSM_STRIDE + col]) * inv0;
                    float f1 = (oacc[mf][nf][1] + osm[r0 * OSM_STRIDE + col + 1]) * inv0;
                    float f2 = (oacc[mf][nf][2] + osm[(r0 + 8) * OSM_STRIDE + col]) * inv1;
                    float f3 = (oacc[mf][nf][3] + osm[(r0 + 8) * OSM_STRIDE + col + 1]) * inv1;
                    ((uint32_t*)oo)[(g0 + col) >> 1] = packh2(__float2half_rn(f0), __float2half_rn(f1));
                    ((uint32_t*)oo)[(g1 + col) >> 1] = packh2(__float2half_rn(f2), __float2half_rn(f3));
                }
            }
        }
        __syncthreads();
    }
}

// ---------------------------------------------------------------------------
extern "C" void kernel_launch(void* const* d_in, const int* in_sizes, int n_in,
                              void* d_out, int out_size)
{
    const float* hidden = (const float*)d_in[0];
    const float* Wq = (const float*)d_in[1];
    const float* Wk = (const float*)d_in[2];
    const float* Wv = (const float*)d_in[3];
    const float* Wo = (const float*)d_in[4];
    float* out = (float*)d_out;

    fp16 *hhi, *hlo, *qhi, *qlo, *kk, *vv, *oo;
    cudaGetSymbolAddress((void**)&hhi, g_hhi);
    cudaGetSymbolAddress((void**)&hlo, g_hlo);
    cudaGetSymbolAddress((void**)&qhi, g_qhi);
    cudaGetSymbolAddress((void**)&qlo, g_qlo);
    cudaGetSymbolAddress((void**)&kk, g_k);
    cudaGetSymbolAddress((void**)&vv, g_v);
    cudaGetSymbolAddress((void**)&oo, g_o);
    fp16 *wqh, *wql, *wkh, *wkl, *wvt, *wot;
    cudaGetSymbolAddress((void**)&wqh, g_wqt_hi);
    cudaGetSymbolAddress((void**)&wql, g_wqt_lo);
    cudaGetSymbolAddress((void**)&wkh, g_wkt_hi);
    cudaGetSymbolAddress((void**)&wkl, g_wkt_lo);
    cudaGetSymbolAddress((void**)&wvt, g_wvt);
    cudaGetSymbolAddress((void**)&wot, g_wot);

    cudaFuncSetAttribute(gemm_qk, cudaFuncAttributeMaxDynamicSharedMemorySize, QK_SMEM);
    cudaFuncSetAttribute(gemm_v, cudaFuncAttributeMaxDynamicSharedMemorySize, GEMM1_SMEM);
    cudaFuncSetAttribute(gemm_out, cudaFuncAttributeMaxDynamicSharedMemorySize, GEMM1_SMEM);
    cudaFuncSetAttribute(attn_mma, cudaFuncAttributeMaxDynamicSharedMemorySize, ATT_SMEM);

    convert_all<<<dim3(32, 32, 5), dim3(32, 8)>>>(hidden, Wq, Wk, Wv, Wo,
        hhi, hlo, wqh, wql, wkh, wkl, wvt, wot);

    gemm_qk<<<256, 256, QK_SMEM>>>(hhi, hlo, wqh, wql, wkh, wkl, qhi, qlo, kk);
    gemm_v<<<dim3(8, 32), 256, GEMM1_SMEM>>>(hhi, wvt, vv);
    attn_mma<<<dim3(8, Hh, Bb), 256, ATT_SMEM>>>(qhi, qlo, kk, vv, oo);
    gemm_out<<<dim3(8, 32), 256, GEMM1_SMEM>>>(oo, wot, out);
}

// round 16
// speedup vs baseline: 2.0440x; 1.0943x over previous
#include <cuda_runtime.h>
#include <cuda_fp16.h>
#include <stdint.h>

// ReBasedLinearAttention: B=2, L=2048, D=1024, H=16, FD=16, HD=64
// fp16 mma.sync at HMMA issue floor. Precision plan:
//   Q/K proj: 3-term compute, q & k stored SINGLE fp16
//   QK^T    : 1-term; V proj, SV, Out: 1-term; z exact fp32

#define Bb 2
#define Ll 2048
#define Dd 1024
#define Hh 16
#define BL (Bb * Ll)

typedef unsigned long long ull;
typedef __half fp16;

// ---------------- scratch ----------------
__device__ fp16 g_hhi[BL * 1024];
__device__ fp16 g_hlo[BL * 1024];
__device__ fp16 g_q[BL * 256];
__device__ fp16 g_k[BL * 256];
__device__ fp16 g_v[BL * 1024];
__device__ fp16 g_o[BL * 1024];

__device__ fp16 g_wqt_hi[256 * 1024];
__device__ fp16 g_wqt_lo[256 * 1024];
__device__ fp16 g_wkt_hi[256 * 1024];
__device__ fp16 g_wkt_lo[256 * 1024];
__device__ fp16 g_wvt[1024 * 1024];
__device__ fp16 g_wot[1024 * 1024];

// ---------------- PTX helpers ----------------
__device__ __forceinline__ uint32_t smem_u32(const void* p) {
    uint32_t a;
    asm("{ .reg .u64 t; cvta.to.shared.u64 t, %1; cvt.u32.u64 %0, t; }" : "=r"(a) : "l"(p));
    return a;
}
__device__ __forceinline__ void cp_async16(uint32_t saddr, const void* gaddr) {
    asm volatile("cp.async.cg.shared.global [%0], [%1], 16;" :: "r"(saddr), "l"(gaddr) : "memory");
}
__device__ __forceinline__ void cp_commit() {
    asm volatile("cp.async.commit_group;" ::: "memory");
}
__device__ __forceinline__ void cp_wait0() {
    asm volatile("cp.async.wait_group 0;" ::: "memory");
}
__device__ __forceinline__ void ldsm_x4(uint32_t& r0, uint32_t& r1, uint32_t& r2, uint32_t& r3,
                                        uint32_t addr) {
    asm volatile("ldmatrix.sync.aligned.m8n8.x4.shared.b16 {%0,%1,%2,%3}, [%4];"
                 : "=r"(r0), "=r"(r1), "=r"(r2), "=r"(r3) : "r"(addr));
}
__device__ __forceinline__ void ldsm_x4_t(uint32_t& r0, uint32_t& r1, uint32_t& r2, uint32_t& r3,
                                          uint32_t addr) {
    asm volatile("ldmatrix.sync.aligned.m8n8.x4.trans.shared.b16 {%0,%1,%2,%3}, [%4];"
                 : "=r"(r0), "=r"(r1), "=r"(r2), "=r"(r3) : "r"(addr));
}
__device__ __forceinline__ void mma16816(float c[4], uint32_t a0, uint32_t a1, uint32_t a2,
                                         uint32_t a3, uint32_t b0, uint32_t b1) {
    asm volatile(
        "mma.sync.aligned.m16n8k16.row.col.f32.f16.f16.f32 "
        "{%0,%1,%2,%3}, {%4,%5,%6,%7}, {%8,%9}, {%0,%1,%2,%3};"
        : "+f"(c[0]), "+f"(c[1]), "+f"(c[2]), "+f"(c[3])
        : "r"(a0), "r"(a1), "r"(a2), "r"(a3), "r"(b0), "r"(b1));
}
__device__ __forceinline__ uint32_t packh2(fp16 lo, fp16 hi) {
    __half2 t = __halves2half2(lo, hi);
    return *reinterpret_cast<uint32_t*>(&t);
}
__device__ __forceinline__ void spl(float x, fp16& h, fp16& l) {
    h = __float2half_rn(x);
    l = __float2half_rn(x - __half2float(h));
}

// ---------------------------------------------------------------------------
// Conversions: z 0=Wq(hi/lo) 1=Wk(hi/lo) 2=Wv(single) 3=Wo(single) 4=hidden split
// ---------------------------------------------------------------------------
__global__ void convert_all(const float* __restrict__ hidden,
                            const float* __restrict__ Wq, const float* __restrict__ Wk,
                            const float* __restrict__ Wv, const float* __restrict__ Wo,
                            fp16* __restrict__ hh, fp16* __restrict__ hl,
                            fp16* __restrict__ qh, fp16* __restrict__ ql,
                            fp16* __restrict__ kh, fp16* __restrict__ kl,
                            fp16* __restrict__ vt, fp16* __restrict__ ot)
{
    const int z = blockIdx.z;
    const int tid = threadIdx.y * 32 + threadIdx.x;
    if (z == 4) {
        int base = (blockIdx.y * (int)gridDim.x + blockIdx.x) * 1024 + tid * 4;
#pragma unroll
        for (int u = 0; u < 4; u++) {
            int i = base + u;
            float4 v = ((const float4*)hidden)[i];
            float vv[4] = {v.x, v.y, v.z, v.w};
            fp16 hhv[4], llv[4];
#pragma unroll
            for (int j = 0; j < 4; j++) spl(vv[j], hhv[j], llv[j]);
            *(ull*)&hh[(size_t)i * 4] = *(ull*)hhv;
            *(ull*)&hl[(size_t)i * 4] = *(ull*)llv;
        }
        return;
    }
    const int N = (z < 2) ? 256 : 1024;
    if (blockIdx.x * 32 >= N) return;
    const float* W = (z == 0) ? Wq : (z == 1) ? Wk : (z == 2) ? Wv : Wo;

    __shared__ float t[32][33];
    int n0 = blockIdx.x * 32, k0 = blockIdx.y * 32;
    int tx = threadIdx.x, ty = threadIdx.y;
#pragma unroll
    for (int i = 0; i < 4; i++)
        t[ty + i * 8][tx] = W[(size_t)(k0 + ty + i * 8) * N + n0 + tx];
    __syncthreads();
    if (z < 2) {
        fp16* thi = (z == 0) ? qh : kh;
        fp16* tlo = (z == 0) ? ql : kl;
#pragma unroll
        for (int i = 0; i < 4; i++) {
            int r = ty + i * 8;
            fp16 h, l;
            spl(t[tx][r], h, l);
            thi[(size_t)(n0 + r) * 1024 + k0 + tx] = h;
            tlo[(size_t)(n0 + r) * 1024 + k0 + tx] = l;
        }
    } else {
        fp16* ts = (z == 2) ? vt : ot;
#pragma unroll
        for (int i = 0; i < 4; i++) {
            int r = ty + i * 8;
            ts[(size_t)(n0 + r) * 1024 + k0 + tx] = __float2half_rn(t[tx][r]);
        }
    }
}

// ---------------------------------------------------------------------------
// Tile geometry constants
// ---------------------------------------------------------------------------
#define ROWB 80
#define QK_A_MATB (64 * ROWB)
#define QK_B_MATB (128 * ROWB)
#define QK_BOFF (2 * QK_A_MATB)
#define QK_STAGEB (2 * QK_A_MATB + 2 * QK_B_MATB)   // 30720
#define QK_SMEM (2 * QK_STAGEB)                     // 61440
#define MATB (128 * ROWB)
#define STAGEB1 (2 * MATB)
#define GEMM1_SMEM (2 * STAGEB1)                    // 40960

// ---------------------------------------------------------------------------
// Merged QKV projection (512 CTAs):
//  t in [0,256): Q/K 3-term, 64x128 tile; [0,128) Q (x0.25, single out),
//                [128,256) K (single out).
//  t in [256,512): V 1-term, 128x128 tile.
// ---------------------------------------------------------------------------
__global__ __launch_bounds__(256, 2)
void gemm_qkv(const fp16* __restrict__ Ahi, const fp16* __restrict__ Alo,
              const fp16* __restrict__ qwh, const fp16* __restrict__ qwl,
              const fp16* __restrict__ kwh, const fp16* __restrict__ kwl,
              const fp16* __restrict__ wv,
              fp16* __restrict__ qs, fp16* __restrict__ ks, fp16* __restrict__ V)
{
    extern __shared__ char smem_raw[];
    const uint32_t sbase = smem_u32(smem_raw);
    const int tid = threadIdx.x;
    const int lane = tid & 31;
    const int warp = tid >> 5;
    const int lrow = lane & 15;
    const int lkb = ((lane >> 4) & 1) * 16;

    int t = blockIdx.x;
    if (t < 256) {
        // ================= Q/K path (3-term) =================
        const bool isQ = (t < 128);
        if (!isQ) t -= 128;
        const fp16* Bhi = isQ ? qwh : kwh;
        const fp16* Blo = isQ ? qwl : kwl;
        fp16* Cs = isQ ? qs : ks;
        const float cs = isQ ? 0.25f : 1.f;
        const int N = 256;
        const int bx = t & 1, by = t >> 1;
        const int rowBase = by * 64;
        const int colBase = bx * 128;
        const int wm = warp >> 2;
        const int wn = warp & 3;

        float acc[2][4][4];
#pragma unroll
        for (int i = 0; i < 2; i++)
#pragma unroll
            for (int j = 0; j < 4; j++)
#pragma unroll
                for (int e = 0; e < 4; e++) acc[i][j][e] = 0.f;

#define QK_LOAD(s, buf)                                                                 \
    do {                                                                                \
        const int k0 = (s) * 32;                                                        \
        const uint32_t sb_ = sbase + (buf) * QK_STAGEB;                                 \
        _Pragma("unroll")                                                               \
        for (int tt = 0; tt < 6; tt++) {                                                \
            int idx = tt * 256 + tid;                                                   \
            if (idx < 512) {                                                            \
                int mat = idx >> 8;                                                     \
                int rem = idx & 255;                                                    \
                int row = rem >> 2;                                                     \
                int kc = rem & 3;                                                       \
                const fp16* src = mat ? Alo : Ahi;                                      \
                cp_async16(sb_ + mat * QK_A_MATB + row * ROWB + kc * 16,                \
                           src + (size_t)(rowBase + row) * 1024 + k0 + kc * 8);         \
            } else {                                                                    \
                int idx2 = idx - 512;                                                   \
                int mat = idx2 >> 9;                                                    \
                int rem = idx2 & 511;                                                   \
                int row = rem >> 2;                                                     \
                int kc = rem & 3;                                                       \
                const fp16* src = mat ? Blo : Bhi;                                      \
                cp_async16(sb_ + QK_BOFF + mat * QK_B_MATB + row * ROWB + kc * 16,      \
                           src + (size_t)(colBase + row) * 1024 + k0 + kc * 8);         \
            }                                                                           \
        }                                                                               \
        cp_commit();                                                                    \
    } while (0)

        QK_LOAD(0, 0);
        for (int s = 0; s < 32; s++) {
            cp_wait0();
            __syncthreads();
            if (s + 1 < 32) QK_LOAD(s + 1, (s + 1) & 1);
            const uint32_t sb = sbase + (s & 1) * QK_STAGEB;
#pragma unroll
            for (int s2 = 0; s2 < 2; s2++) {
                const uint32_t kbyte = s2 * 32 + lkb;
                uint32_t Ah[2][4], Al[2][4];
#pragma unroll
                for (int mf = 0; mf < 2; mf++) {
                    uint32_t ra = sb + (uint32_t)((wm * 32 + mf * 16 + lrow) * ROWB) + kbyte;
                    ldsm_x4(Ah[mf][0], Ah[mf][1], Ah[mf][2], Ah[mf][3], ra);
                    ldsm_x4(Al[mf][0], Al[mf][1], Al[mf][2], Al[mf][3], ra + QK_A_MATB);
                }
                uint32_t Bh[4][2], Blr[4][2];
#pragma unroll
                for (int nf2 = 0; nf2 < 2; nf2++) {
                    uint32_t rb = sb + QK_BOFF +
                                  (uint32_t)((wn * 32 + nf2 * 16 + lrow) * ROWB) + kbyte;
                    uint32_t q0, q1, q2, q3;
                    ldsm_x4(q0, q1, q2, q3, rb);
                    Bh[nf2 * 2 + 0][0] = q0; Bh[nf2 * 2 + 0][1] = q2;
                    Bh[nf2 * 2 + 1][0] = q1; Bh[nf2 * 2 + 1][1] = q3;
                    ldsm_x4(q0, q1, q2, q3, rb + QK_B_MATB);
                    Blr[nf2 * 2 + 0][0] = q0; Blr[nf2 * 2 + 0][1] = q2;
                    Blr[nf2 * 2 + 1][0] = q1; Blr[nf2 * 2 + 1][1] = q3;
                }
#pragma unroll
                for (int mf = 0; mf < 2; mf++)
#pragma unroll
                    for (int nf = 0; nf < 4; nf++) {
                        mma16816(acc[mf][nf], Ah[mf][0], Ah[mf][1], Ah[mf][2], Ah[mf][3],
                                 Bh[nf][0], Bh[nf][1]);
                        mma16816(acc[mf][nf], Ah[mf][0], Ah[mf][1], Ah[mf][2], Ah[mf][3],
                                 Blr[nf][0], Blr[nf][1]);
                        mma16816(acc[mf][nf], Al[mf][0], Al[mf][1], Al[mf][2], Al[mf][3],
                                 Bh[nf][0], Bh[nf][1]);
                    }
            }
        }

        const int r0b = rowBase + wm * 32 + (lane >> 2);
        const int c0b = colBase + wn * 32 + (lane & 3) * 2;
#pragma unroll
        for (int mf = 0; mf < 2; mf++) {
#pragma unroll
            for (int nf = 0; nf < 4; nf++) {
                int r = r0b + mf * 16;
                int c = c0b + nf * 8;
                ((uint32_t*)Cs)[((size_t)r * N + c) >> 1] =
                    packh2(__float2half_rn(acc[mf][nf][0] * cs),
                           __float2half_rn(acc[mf][nf][1] * cs));
                ((uint32_t*)Cs)[((size_t)(r + 8) * N + c) >> 1] =
                    packh2(__float2half_rn(acc[mf][nf][2] * cs),
                           __float2half_rn(acc[mf][nf][3] * cs));
            }
        }
    } else {
        // ================= V path (1-term) =================
        t -= 256;
        const int bx = t & 7, by = t >> 3;
        const int rowBase = by * 128;
        const int colBase = bx * 128;
        const int N = 1024;
        const int wm = warp >> 2;
        const int wn = warp & 3;

        float acc[4][4][4];
#pragma unroll
        for (int i = 0; i < 4; i++)
#pragma unroll
            for (int j = 0; j < 4; j++)
#pragma unroll
                for (int e = 0; e < 4; e++) acc[i][j][e] = 0.f;

#define V_LOAD(s, buf)                                                                  \
    do {                                                                                \
        const int k0 = (s) * 32;                                                        \
        const uint32_t sb_ = sbase + (buf) * STAGEB1;                                   \
        _Pragma("unroll")                                                               \
        for (int tt = 0; tt < 4; tt++) {                                                \
            int idx = tt * 256 + tid;                                                   \
            int mat = idx >> 9;                                                         \
            int rem = idx & 511;                                                        \
            int row = rem >> 2;                                                         \
            int kc = rem & 3;                                                           \
            const fp16* src = (mat == 0) ? Ahi : wv;                                    \
            int grow = ((mat == 0) ? rowBase : colBase) + row;                          \
            cp_async16(sb_ + mat * MATB + row * ROWB + kc * 16,                         \
                       src + (size_t)grow * 1024 + k0 + kc * 8);                        \
        }                                                                               \
        cp_commit();                                                                    \
    } while (0)

        V_LOAD(0, 0);
        for (int s = 0; s < 32; s++) {
            cp_wait0();
            __syncthreads();
            if (s + 1 < 32) V_LOAD(s + 1, (s + 1) & 1);
            const uint32_t sb = sbase + (s & 1) * STAGEB1;
#pragma unroll
            for (int s2 = 0; s2 < 2; s2++) {
                const uint32_t kbyte = s2 * 32 + lkb;
                uint32_t Ah[4][4];
#pragma unroll
                for (int mf = 0; mf < 4; mf++) {
                    uint32_t ra = sb + (uint32_t)((wm * 64 + mf * 16 + lrow) * ROWB) + kbyte;
                    ldsm_x4(Ah[mf][0], Ah[mf][1], Ah[mf][2], Ah[mf][3], ra);
                }
                uint32_t Bv[4][2];
#pragma unroll
                for (int nf2 = 0; nf2 < 2; nf2++) {
                    uint32_t rb = sb + MATB +
                                  (uint32_t)((wn * 32 + nf2 * 16 + lrow) * ROWB) + kbyte;
                    uint32_t q0, q1, q2, q3;
                    ldsm_x4(q0, q1, q2, q3, rb);
                    Bv[nf2 * 2 + 0][0] = q0; Bv[nf2 * 2 + 0][1] = q2;
                    Bv[nf2 * 2 + 1][0] = q1; Bv[nf2 * 2 + 1][1] = q3;
                }
#pragma unroll
                for (int mf = 0; mf < 4; mf++)
#pragma unroll
                    for (int nf = 0; nf < 4; nf++)
                        mma16816(acc[mf][nf], Ah[mf][0], Ah[mf][1], Ah[mf][2], Ah[mf][3],
                                 Bv[nf][0], Bv[nf][1]);
            }
        }

        const int r0b = rowBase + wm * 64 + (lane >> 2);
        const int c0b = colBase + wn * 32 + (lane & 3) * 2;
#pragma unroll
        for (int mf = 0; mf < 4; mf++) {
#pragma unroll
            for (int nf = 0; nf < 4; nf++) {
                int r = r0b + mf * 16;
                int c = c0b + nf * 8;
                ((uint32_t*)V)[((size_t)r * N + c) >> 1] =
                    packh2(__float2half_rn(acc[mf][nf][0]), __float2half_rn(acc[mf][nf][1]));
                ((uint32_t*)V)[((size_t)(r + 8) * N + c) >> 1] =
                    packh2(__float2half_rn(acc[mf][nf][2]), __float2half_rn(acc[mf][nf][3]));
            }
        }
    }
}

// ---------------------------------------------------------------------------
// O projection (1-term): out = o @ Wo, fp32 out.
// ---------------------------------------------------------------------------
__global__ __launch_bounds__(256, 2)
void gemm_out(const fp16* __restrict__ As, const fp16* __restrict__ Bs, float* __restrict__ C)
{
    extern __shared__ char smem_raw[];
    const uint32_t sbase = smem_u32(smem_raw);
    const int tid = threadIdx.x;
    const int lane = tid & 31;
    const int warp = tid >> 5;
    const int wm = warp >> 2;
    const int wn = warp & 3;
    const int rowBase = blockIdx.y * 128;
    const int colBase = blockIdx.x * 128;
    const int N = 1024;

    float acc[4][4][4];
#pragma unroll
    for (int i = 0; i < 4; i++)
#pragma unroll
        for (int j = 0; j < 4; j++)
#pragma unroll
            for (int e = 0; e < 4; e++) acc[i][j][e] = 0.f;

    const int lrow = lane & 15;
    const int lkb = ((lane >> 4) & 1) * 16;

#define O_LOAD(s, buf)                                                                  \
    do {                                                                                \
        const int k0 = (s) * 32;                                                        \
        const uint32_t sb_ = sbase + (buf) * STAGEB1;                                   \
        _Pragma("unroll")                                                               \
        for (int tt = 0; tt < 4; tt++) {                                                \
            int idx = tt * 256 + tid;                                                   \
            int mat = idx >> 9;                                                         \
            int rem = idx & 511;                                                        \
            int row = rem >> 2;                                                         \
            int kc = rem & 3;                                                           \
            const fp16* src = (mat == 0) ? As : Bs;                                     \
            int grow = ((mat == 0) ? rowBase : colBase) + row;                          \
            cp_async16(sb_ + mat * MATB + row * ROWB + kc * 16,                         \
                       src + (size_t)grow * 1024 + k0 + kc * 8);                        \
        }                                                                               \
        cp_commit();                                                                    \
    } while (0)

    O_LOAD(0, 0);
    for (int s = 0; s < 32; s++) {
        cp_wait0();
        __syncthreads();
        if (s + 1 < 32) O_LOAD(s + 1, (s + 1) & 1);
        const uint32_t sb = sbase + (s & 1) * STAGEB1;
#pragma unroll
        for (int s2 = 0; s2 < 2; s2++) {
            const uint32_t kbyte = s2 * 32 + lkb;
            uint32_t Ah[4][4];
#pragma unroll
            for (int mf = 0; mf < 4; mf++) {
                uint32_t ra = sb + (uint32_t)((wm * 64 + mf * 16 + lrow) * ROWB) + kbyte;
                ldsm_x4(Ah[mf][0], Ah[mf][1], Ah[mf][2], Ah[mf][3], ra);
            }
            uint32_t Bv[4][2];
#pragma unroll
            for (int nf2 = 0; nf2 < 2; nf2++) {
                uint32_t rb = sb + MATB +
                              (uint32_t)((wn * 32 + nf2 * 16 + lrow) * ROWB) + kbyte;
                uint32_t q0, q1, q2, q3;
                ldsm_x4(q0, q1, q2, q3, rb);
                Bv[nf2 * 2 + 0][0] = q0; Bv[nf2 * 2 + 0][1] = q2;
                Bv[nf2 * 2 + 1][0] = q1; Bv[nf2 * 2 + 1][1] = q3;
            }
#pragma unroll
            for (int mf = 0; mf < 4; mf++)
#pragma unroll
                for (int nf = 0; nf < 4; nf++)
                    mma16816(acc[mf][nf], Ah[mf][0], Ah[mf][1], Ah[mf][2], Ah[mf][3],
                             Bv[nf][0], Bv[nf][1]);
        }
    }

    const int r0b = rowBase + wm * 64 + (lane >> 2);
    const int c0b = colBase + wn * 32 + (lane & 3) * 2;
#pragma unroll
    for (int mf = 0; mf < 4; mf++) {
#pragma unroll
        for (int nf = 0; nf < 4; nf++) {
            int r = r0b + mf * 16;
            int c = c0b + nf * 8;
            *(float2*)&C[(size_t)r * N + c] = make_float2(acc[mf][nf][0], acc[mf][nf][1]);
            *(float2*)&C[(size_t)(r + 8) * N + c] = make_float2(acc[mf][nf][2], acc[mf][nf][3]);
        }
    }
}

// ---------------------------------------------------------------------------
// Attention: paired query tiles; 128-key loads; QK 1-term, SV 1-term.
// smem: q +0 (6144); per buffer: k +0 (6144), v +6144 (18432)
// ---------------------------------------------------------------------------
#define SQ 0
#define S_TILES 6144
#define A_BUFSZ 24576
#define ATT_SMEM (S_TILES + 2 * A_BUFSZ)   // 55296
#define SZOFF 33792
#define OSM_STRIDE 66

__global__ __launch_bounds__(256, 2)
void attn_mma(const fp16* __restrict__ qq, const fp16* __restrict__ kk,
              const fp16* __restrict__ vv, fp16* __restrict__ oo)
{
    extern __shared__ char smem_raw[];
    const uint32_t sbase = smem_u32(smem_raw);

    const int pr = blockIdx.x;
    const int h = blockIdx.y;
    const int b = blockIdx.z;

    const int tid = threadIdx.x;
    const int lane = tid & 31;
    const int warp = tid >> 5;
    const int wm = warp >> 1;
    const int wn = warp & 1;
    const int lrow = lane & 15;
    const int lkb = ((lane >> 4) & 1) * 16;
    const int lm = lane >> 3;
    const int lr = lane & 7;

#define ATT_LOAD128(t, bsel)                                                             \
    do {                                                                                 \
        const int j0_ = (t) * 128;                                                       \
        const uint32_t bb = sbase + S_TILES + (bsel) * A_BUFSZ;                          \
        {                                                                                \
            int row = tid >> 1;                                                          \
            int ch = tid & 1;                                                            \
            cp_async16(bb + row * 48 + ch * 16,                                          \
                       kk + (size_t)(b * Ll + j0_ + row) * 256 + h * 16 + ch * 8);       \
        }                                                                                \
        _Pragma("unroll")                                                                \
        for (int t2 = 0; t2 < 4; t2++) {                                                 \
            int idx = t2 * 256 + tid;                                                    \
            int row = idx >> 3;                                                          \
            int ch = idx & 7;                                                            \
            cp_async16(bb + 6144 + row * 144 + ch * 16,                                  \
                       vv + (size_t)(b * Ll + j0_ + row) * 1024 + h * 64 + ch * 8);      \
        }                                                                                \
        cp_commit();                                                                     \
    } while (0)

    for (int half = 0; half < 2; half++) {
        const int qt = (half == 0) ? (15 - pr) : pr;
        const int qi0 = qt * 128;
        const int nt = qt + 1;

        // ---- load q tile (128 x 16, single) ----
        {
            int row = tid >> 1;
            int ch = tid & 1;
            uint4 v = *(const uint4*)&qq[(size_t)(b * Ll + qi0 + row) * 256 + h * 16 + ch * 8];
            *(uint4*)(smem_raw + SQ + row * 48 + ch * 16) = v;
        }
        ATT_LOAD128(0, 0);
        __syncthreads();

        uint32_t Aq[2][4];
#pragma unroll
        for (int mf = 0; mf < 2; mf++) {
            uint32_t ra = sbase + SQ + (uint32_t)((wm * 32 + mf * 16 + lrow) * 48) + lkb;
            ldsm_x4(Aq[mf][0], Aq[mf][1], Aq[mf][2], Aq[mf][3], ra);
        }

        float oacc[2][8][4];
#pragma unroll
        for (int i = 0; i < 2; i++)
#pragma unroll
            for (int j = 0; j < 8; j++)
#pragma unroll
                for (int e = 0; e < 4; e++) oacc[i][j][e] = 0.f;
        float zv[2][2] = {{0.f, 0.f}, {0.f, 0.f}};

        for (int t = 0; t < nt; t++) {
            cp_wait0();
            __syncthreads();
            if (t + 1 < nt) ATT_LOAD128(t + 1, (t + 1) & 1);

            const uint32_t bb = sbase + S_TILES + (t & 1) * A_BUFSZ;

#pragma unroll
            for (int sub = 0; sub < 2; sub++) {
                const int j0 = t * 128 + sub * 64;
                const uint32_t kb = bb + (uint32_t)sub * 3072;
                const uint32_t vb = bb + 6144 + (uint32_t)sub * 9216;

                // ---- QK^T (1-term) ----
                float sacc[2][4][4];
#pragma unroll
                for (int i = 0; i < 2; i++)
#pragma unroll
                    for (int j = 0; j < 4; j++)
#pragma unroll
                        for (int e = 0; e < 4; e++) sacc[i][j][e] = 0.f;

#pragma unroll
                for (int nf2 = 0; nf2 < 2; nf2++) {
                    uint32_t ra = kb + (uint32_t)((wn * 32 + nf2 * 16 + lrow) * 48) + lkb;
                    uint32_t kh0, kh1, kh2, kh3;
                    ldsm_x4(kh0, kh1, kh2, kh3, ra);
#pragma unroll
                    for (int mf = 0; mf < 2; mf++) {
                        mma16816(sacc[mf][nf2 * 2 + 0], Aq[mf][0], Aq[mf][1], Aq[mf][2], Aq[mf][3], kh0, kh2);
                        mma16816(sacc[mf][nf2 * 2 + 1], Aq[mf][0], Aq[mf][1], Aq[mf][2], Aq[mf][3], kh1, kh3);
                    }
                }

                // ---- mask ----
                if (j0 + 64 > qi0) {
                    const int rq = qi0 + wm * 32 + (lane >> 2);
                    const int cb0 = j0 + wn * 32 + (lane & 3) * 2;
#pragma unroll
                    for (int mf = 0; mf < 2; mf++) {
                        const int r0 = rq + mf * 16;
                        const int r1 = r0 + 8;
#pragma unroll
                        for (int nf = 0; nf < 4; nf++) {
                            float* c = sacc[mf][nf];
                            const int cb = cb0 + nf * 8;
                            if (cb > r0) c[0] = 0.f;
                            if (cb + 1 > r0) c[1] = 0.f;
                            if (cb > r1) c[2] = 0.f;
                            if (cb + 1 > r1) c[3] = 0.f;
                        }
                    }
                }

                // ---- square, z (fp32), repack s -> single fp16 ----
                uint32_t Ash[2][2][4];
#pragma unroll
                for (int mf = 0; mf < 2; mf++) {
#pragma unroll
                    for (int nf = 0; nf < 4; nf++) {
                        float* c = sacc[mf][nf];
                        float s0 = c[0] * c[0];
                        float s1 = c[1] * c[1];
                        float s2 = c[2] * c[2];
                        float s3 = c[3] * c[3];
                        zv[mf][0] += s0 + s1;
                        zv[mf][1] += s2 + s3;
                        int kc = nf >> 1, nfs = nf & 1;
                        Ash[mf][kc][nfs * 2 + 0] = packh2(__float2half_rn(s0), __float2half_rn(s1));
                        Ash[mf][kc][nfs * 2 + 1] = packh2(__float2half_rn(s2), __float2half_rn(s3));
                    }
                }

                // ---- SV (1-term) ----
#pragma unroll
                for (int kc = 0; kc < 2; kc++) {
#pragma unroll
                    for (int nf2 = 0; nf2 < 4; nf2++) {
                        uint32_t av = vb +
                                      (uint32_t)((wn * 32 + kc * 16 + (lm & 1) * 8 + lr) * 144) +
                                      (uint32_t)(nf2 * 32 + (lm >> 1) * 16);
                        uint32_t vh0, vh1, vh2, vh3;
                        ldsm_x4_t(vh0, vh1, vh2, vh3, av);
#pragma unroll
                        for (int mf = 0; mf < 2; mf++) {
                            mma16816(oacc[mf][nf2 * 2 + 0], Ash[mf][kc][0], Ash[mf][kc][1], Ash[mf][kc][2], Ash[mf][kc][3], vh0, vh1);
                            mma16816(oacc[mf][nf2 * 2 + 1], Ash[mf][kc][0], Ash[mf][kc][1], Ash[mf][kc][2], Ash[mf][kc][3], vh2, vh3);
                        }
                    }
                }
            }
        }
        __syncthreads();

        // ---- epilogue ----
#pragma unroll
        for (int mf = 0; mf < 2; mf++)
#pragma unroll
            for (int hf = 0; hf < 2; hf++) {
                zv[mf][hf] += __shfl_xor_sync(0xffffffffu, zv[mf][hf], 1);
                zv[mf][hf] += __shfl_xor_sync(0xffffffffu, zv[mf][hf], 2);
            }

        float* osm = (float*)smem_raw;
        float* zsm = (float*)(smem_raw + SZOFF);

        if (wn == 0) {
#pragma unroll
            for (int mf = 0; mf < 2; mf++) {
                int r0 = wm * 32 + mf * 16 + (lane >> 2);
#pragma unroll
                for (int nf = 0; nf < 8; nf++) {
                    int col = nf * 8 + (lane & 3) * 2;
                    *(float2*)&osm[r0 * OSM_STRIDE + col] = make_float2(oacc[mf][nf][0], oacc[mf][nf][1]);
                    *(float2*)&osm[(r0 + 8) * OSM_STRIDE + col] = make_float2(oacc[mf][nf][2], oacc[mf][nf][3]);
                }
                if ((lane & 3) == 0) {
                    zsm[r0] = zv[mf][0];
                    zsm[r0 + 8] = zv[mf][1];
                }
            }
        }
        __syncthreads();
        if (wn == 1) {
#pragma unroll
            for (int mf = 0; mf < 2; mf++) {
                int r0 = wm * 32 + mf * 16 + (lane >> 2);
                float inv0 = 1.f / (zv[mf][0] + zsm[r0] + 1e-5f);
                float inv1 = 1.f / (zv[mf][1] + zsm[r0 + 8] + 1e-5f);
                size_t g0 = (size_t)(b * Ll + qi0 + r0) * 1024 + h * 64;
                size_t g1 = (size_t)(b * Ll + qi0 + r0 + 8) * 1024 + h * 64;
#pragma unroll
                for (int nf = 0; nf < 8; nf++) {
                    int col = nf * 8 + (lane & 3) * 2;
                    float f0 = (oacc[mf][nf][0] + osm[r0 * OSM_STRIDE + col]) * inv0;
                    float f1 = (oacc[mf][nf][1] + osm[r0 * OSM_STRIDE + col + 1]) * inv0;
                    float f2 = (oacc[mf][nf][2] + osm[(r0 + 8) * OSM_STRIDE + col]) * inv1;
                    float f3 = (oacc[mf][nf][3] + osm[(r0 + 8) * OSM_STRIDE + col + 1]) * inv1;
                    ((uint32_t*)oo)[(g0 + col) >> 1] = packh2(__float2half_rn(f0), __float2half_rn(f1));
                    ((uint32_t*)oo)[(g1 + col) >> 1] = packh2(__float2half_rn(f2), __float2half_rn(f3));
                }
            }
        }
        __syncthreads();
    }
}

// ---------------------------------------------------------------------------
extern "C" void kernel_launch(void* const* d_in, const int* in_sizes, int n_in,
                              void* d_out, int out_size)
{
    const float* hidden = (const float*)d_in[0];
    const float* Wq = (const float*)d_in[1];
    const float* Wk = (const float*)d_in[2];
    const float* Wv = (const float*)d_in[3];
    const float* Wo = (const float*)d_in[4];
    float* out = (float*)d_out;

    fp16 *hhi, *hlo, *qq, *kk, *vv, *oo;
    cudaGetSymbolAddress((void**)&hhi, g_hhi);
    cudaGetSymbolAddress((void**)&hlo, g_hlo);
    cudaGetSymbolAddress((void**)&qq, g_q);
    cudaGetSymbolAddress((void**)&kk, g_k);
    cudaGetSymbolAddress((void**)&vv, g_v);
    cudaGetSymbolAddress((void**)&oo, g_o);
    fp16 *wqh, *wql, *wkh, *wkl, *wvt, *wot;
    cudaGetSymbolAddress((void**)&wqh, g_wqt_hi);
    cudaGetSymbolAddress((void**)&wql, g_wqt_lo);
    cudaGetSymbolAddress((void**)&wkh, g_wkt_hi);
    cudaGetSymbolAddress((void**)&wkl, g_wkt_lo);
    cudaGetSymbolAddress((void**)&wvt, g_wvt);
    cudaGetSymbolAddress((void**)&wot, g_wot);

    cudaFuncSetAttribute(gemm_qkv, cudaFuncAttributeMaxDynamicSharedMemorySize, QK_SMEM);
    cudaFuncSetAttribute(gemm_out, cudaFuncAttributeMaxDynamicSharedMemorySize, GEMM1_SMEM);
    cudaFuncSetAttribute(attn_mma, cudaFuncAttributeMaxDynamicSharedMemorySize, ATT_SMEM);

    convert_all<<<dim3(32, 32, 5), dim3(32, 8)>>>(hidden, Wq, Wk, Wv, Wo,
        hhi, hlo, wqh, wql, wkh, wkl, wvt, wot);

    gemm_qkv<<<512, 256, QK_SMEM>>>(hhi, hlo, wqh, wql, wkh, wkl, wvt, qq, kk, vv);
    attn_mma<<<dim3(8, Hh, Bb), 256, ATT_SMEM>>>(qq, kk, vv, oo);
    gemm_out<<<dim3(8, 32), 256, GEMM1_SMEM>>>(oo, wot, out);
}